// round 4
// baseline (speedup 1.0000x reference)
#include <cuda_runtime.h>
#include <math.h>
#include <stdint.h>

#define D_MODEL 1024
#define NH 16
#define HD 64
#define BSZ 2
#define SEQL 2048
#define MTOT (BSZ*SEQL)

// scratch (allocation-free) — q/k/v/attn/xc/wc hold tf32-rounded fp32 bits
__device__ float g_q[(size_t)BSZ*NH*SEQL*HD];
__device__ float g_k[(size_t)BSZ*NH*SEQL*HD];
__device__ float g_v[(size_t)BSZ*NH*SEQL*HD];
__device__ float g_attn[(size_t)MTOT*D_MODEL];
__device__ float g_xc[(size_t)MTOT*D_MODEL];
__device__ float g_wc[4][(size_t)D_MODEL*D_MODEL];

// log2(e)/8 : folded into Q so softmax uses exp2
#define QSCALE 0.18033688011112042f

__device__ __forceinline__ uint32_t f2tf32(float x) {
    uint32_t r;
    asm("cvt.rna.tf32.f32 %0, %1;" : "=r"(r) : "f"(x));
    return r;
}

__device__ __forceinline__ void mma_tf32(float* c, uint32_t a0, uint32_t a1,
                                         uint32_t a2, uint32_t a3,
                                         uint32_t b0, uint32_t b1) {
    asm volatile(
        "mma.sync.aligned.m16n8k8.row.col.f32.tf32.tf32.f32 "
        "{%0,%1,%2,%3}, {%4,%5,%6,%7}, {%8,%9}, {%0,%1,%2,%3};"
        : "+f"(c[0]), "+f"(c[1]), "+f"(c[2]), "+f"(c[3])
        : "r"(a0), "r"(a1), "r"(a2), "r"(a3), "r"(b0), "r"(b1));
}

__device__ __forceinline__ void cpa16(uint32_t dst, const void* src) {
    asm volatile("cp.async.cg.shared.global [%0], [%1], 16;" :: "r"(dst), "l"(src));
}
__device__ __forceinline__ void cpa_commit() { asm volatile("cp.async.commit_group;"); }
__device__ __forceinline__ void cpa_wait1()  { asm volatile("cp.async.wait_group 1;"); }
__device__ __forceinline__ void cpa_wait0()  { asm volatile("cp.async.wait_group 0;"); }

// ---------------------------------------------------------------------------
// tf32 convert passes
// ---------------------------------------------------------------------------
__global__ void cvt1_kernel(const float4* __restrict__ src, float4* __restrict__ dst, int n4)
{
    int i = blockIdx.x * blockDim.x + threadIdx.x;
    if (i < n4) {
        float4 v = src[i];
        v.x = __uint_as_float(f2tf32(v.x));
        v.y = __uint_as_float(f2tf32(v.y));
        v.z = __uint_as_float(f2tf32(v.z));
        v.w = __uint_as_float(f2tf32(v.w));
        dst[i] = v;
    }
}

__global__ void cvt4_kernel(const float4* __restrict__ w0, const float4* __restrict__ w1,
                            const float4* __restrict__ w2, const float4* __restrict__ w3)
{
    int z = blockIdx.y;
    const float4* src = z == 0 ? w0 : z == 1 ? w1 : z == 2 ? w2 : w3;
    float4* dst = (float4*)g_wc[z];
    int i = blockIdx.x * blockDim.x + threadIdx.x;
    float4 v = src[i];
    v.x = __uint_as_float(f2tf32(v.x));
    v.y = __uint_as_float(f2tf32(v.y));
    v.z = __uint_as_float(f2tf32(v.z));
    v.w = __uint_as_float(f2tf32(v.w));
    dst[i] = v;
}

// ---------------------------------------------------------------------------
// tf32 GEMM: Y[m,n] = sum_k A[m,k] * W[n,k]  (A, W already tf32-rounded bits)
// 128x128 tile, BK=32, 256 threads, warp tile 64x32.
// mode 0: plain fp32; 1: RoPE*QSCALE + tf32 scatter (Q);
// 3: RoPE + tf32 scatter (K); 2: tf32 scatter (V)
// ---------------------------------------------------------------------------
#define GSTR 36
#define GSTAGE 4608
#define GEMM_SMEM (2*2*GSTAGE*4)

__global__ __launch_bounds__(256)
void gemm_tf32(const float* __restrict__ A,
               const float* __restrict__ W0, const float* __restrict__ W1,
               const float* __restrict__ W2,
               float* __restrict__ o0, float* __restrict__ o1, float* __restrict__ o2,
               int md0, int md1, int md2, const int* __restrict__ tokpos)
{
    extern __shared__ float sm[];
    const int z = blockIdx.z;
    const float* W = z == 0 ? W0 : z == 1 ? W1 : W2;
    float* out     = z == 0 ? o0 : z == 1 ? o1 : o2;
    const int mode = z == 0 ? md0 : z == 1 ? md1 : md2;

    const int tid = (int)threadIdx.x;
    const int m0 = blockIdx.y * 128, n0 = blockIdx.x * 128;
    const int lane = tid & 31, wid = tid >> 5;
    const int g = lane >> 2, t = lane & 3;
    const int wm = (wid >> 2) * 64, wn = (wid & 3) * 32;

    const int c4 = (tid & 7) * 4;
    const int r0 = tid >> 3;
    uint32_t sbase = (uint32_t)__cvta_generic_to_shared(sm);

    float c[4][4][4];
#pragma unroll
    for (int i = 0; i < 4; ++i)
#pragma unroll
        for (int j = 0; j < 4; ++j)
#pragma unroll
            for (int k = 0; k < 4; ++k) c[i][j][k] = 0.f;

#define ISSUE(stage, k0)                                                         \
    {                                                                            \
        uint32_t as_ = sbase + (uint32_t)(stage) * (2 * GSTAGE * 4);             \
        uint32_t bs_ = as_ + GSTAGE * 4;                                         \
        _Pragma("unroll")                                                        \
        for (int i_ = 0; i_ < 4; ++i_) {                                         \
            int row_ = r0 + 32 * i_;                                             \
            cpa16(as_ + (uint32_t)(row_ * GSTR + c4) * 4,                        \
                  A + (size_t)(m0 + row_) * D_MODEL + (k0) + c4);                \
            cpa16(bs_ + (uint32_t)(row_ * GSTR + c4) * 4,                        \
                  W + (size_t)(n0 + row_) * D_MODEL + (k0) + c4);                \
        }                                                                        \
        cpa_commit();                                                            \
    }

    ISSUE(0, 0);
    ISSUE(1, 32);

    for (int kt = 0; kt < 32; ++kt) {
        cpa_wait1();
        __syncthreads();
        const float* As = sm + (kt & 1) * (2 * GSTAGE);
        const float* Bs = As + GSTAGE;

#pragma unroll
        for (int ks = 0; ks < 4; ++ks) {
            uint32_t af[4][4], bf[4][2];
#pragma unroll
            for (int mt = 0; mt < 4; ++mt) {
                const float* p = As + (wm + mt * 16 + g) * GSTR + ks * 8 + t;
                af[mt][0] = __float_as_uint(p[0]);
                af[mt][1] = __float_as_uint(p[8 * GSTR]);
                af[mt][2] = __float_as_uint(p[4]);
                af[mt][3] = __float_as_uint(p[8 * GSTR + 4]);
            }
#pragma unroll
            for (int nt = 0; nt < 4; ++nt) {
                const float* p = Bs + (wn + nt * 8 + g) * GSTR + ks * 8 + t;
                bf[nt][0] = __float_as_uint(p[0]);
                bf[nt][1] = __float_as_uint(p[4]);
            }
#pragma unroll
            for (int mt = 0; mt < 4; ++mt)
#pragma unroll
                for (int nt = 0; nt < 4; ++nt)
                    mma_tf32(c[mt][nt], af[mt][0], af[mt][1], af[mt][2], af[mt][3],
                             bf[nt][0], bf[nt][1]);
        }
        __syncthreads();
        if (kt + 2 < 32) { ISSUE(kt & 1, (kt + 2) * 32); }
        else             { cpa_commit(); }
    }

    if (mode == 0) {
#pragma unroll
        for (int mt = 0; mt < 4; ++mt) {
            int rowa = m0 + wm + mt * 16 + g;
#pragma unroll
            for (int nt = 0; nt < 4; ++nt) {
                int col = n0 + wn + nt * 8 + 2 * t;
                *(float2*)(out + (size_t)rowa * D_MODEL + col) =
                    make_float2(c[mt][nt][0], c[mt][nt][1]);
                *(float2*)(out + (size_t)(rowa + 8) * D_MODEL + col) =
                    make_float2(c[mt][nt][2], c[mt][nt][3]);
            }
        }
    } else {
#pragma unroll
        for (int mt = 0; mt < 4; ++mt) {
#pragma unroll
            for (int half = 0; half < 2; ++half) {
                int m = m0 + wm + mt * 16 + g + half * 8;
                int b = m >> 11;
                int s = m & (SEQL - 1);
                float pos = (float)tokpos[s];
#pragma unroll
                for (int nt = 0; nt < 4; ++nt) {
                    int col = n0 + wn + nt * 8 + 2 * t;   // even
                    int h = col >> 6;
                    int d = col & 63;
                    float e = c[mt][nt][half * 2 + 0];
                    float o = c[mt][nt][half * 2 + 1];
                    size_t dst = ((size_t)(b * NH + h) * SEQL + s) * HD + d;
                    if (mode != 2) {
                        float fr = exp2f((float)d * (-13.287712379549449f / 64.f));
                        float cs, sn;
                        sincosf(pos * fr, &sn, &cs);
                        float re = e * cs - o * sn;
                        float ro = e * sn + o * cs;
                        if (mode == 1) { re *= QSCALE; ro *= QSCALE; }
                        *(float2*)(out + dst) = make_float2(
                            __uint_as_float(f2tf32(re)), __uint_as_float(f2tf32(ro)));
                    } else {
                        *(float2*)(out + dst) = make_float2(
                            __uint_as_float(f2tf32(e)), __uint_as_float(f2tf32(o)));
                    }
                }
            }
        }
    }
}

// ---------------------------------------------------------------------------
// Flash attention, tf32 mma. CTA: 256 threads (8 warps), QT=128, KT=64.
// Warp w owns q rows [16w,16w+16). Q frags in regs; K/V double-buffered via
// cp.async; P staged per-warp in sP (128 rows).
// Q holds tf32(rope(q) * log2e/8); probs via exp2.
// ---------------------------------------------------------------------------
#define FSTR 68
#define FLASH_SMEM ((4*64 + 128) * FSTR * 4)   // K0,K1,V0,V1 (64 rows each) + sP(128)

__device__ __forceinline__ void kv_issue(uint32_t sbase, int stage,
                                         const float* Kp, const float* Vp,
                                         int tile, int tid)
{
    uint32_t dK = sbase + (uint32_t)(stage * 64 * FSTR) * 4;
    uint32_t dV = sbase + (uint32_t)((2 + stage) * 64 * FSTR) * 4;
#pragma unroll
    for (int i = 0; i < 4; ++i) {
        int lin = tid + i * 256;
        int row = lin >> 4;
        int cc = (lin & 15) * 4;
        cpa16(dK + (uint32_t)(row * FSTR + cc) * 4,
              Kp + (size_t)(tile * 64 + row) * HD + cc);
        cpa16(dV + (uint32_t)(row * FSTR + cc) * 4,
              Vp + (size_t)(tile * 64 + row) * HD + cc);
    }
    cpa_commit();
}

__global__ __launch_bounds__(256, 2)
void flash_mma(float* __restrict__ attnout)
{
    extern __shared__ float sm[];
    float* sP = sm + 4 * 64 * FSTR;
    uint32_t sbase = (uint32_t)__cvta_generic_to_shared(sm);

    const int qt = (int)blockIdx.x;           // q tile of 128
    const int bh = (int)blockIdx.y;
    const int b  = bh >> 4;
    const int h  = bh & 15;
    const int tid = (int)threadIdx.x;
    const int wid = tid >> 5, lane = tid & 31;
    const int g = lane >> 2, t = lane & 3;
    const int wm = wid * 16;                  // warp's first q row within tile

    const float* Qp = g_q + (size_t)bh * SEQL * HD;
    const float* Kp = g_k + (size_t)bh * SEQL * HD;
    const float* Vp = g_v + (size_t)bh * SEQL * HD;

    // stage Q tile (128x64) in sP, pick up A-fragments into registers
#pragma unroll
    for (int i = 0; i < 8; ++i) {
        int lin = tid + i * 256;
        int row = lin >> 4;
        int cc = (lin & 15) * 4;
        *(float4*)&sP[row * FSTR + cc] =
            *(const float4*)(Qp + (size_t)(qt * 128 + row) * HD + cc);
    }
    __syncthreads();
    uint32_t aq[8][4];
#pragma unroll
    for (int ks = 0; ks < 8; ++ks) {
        const float* p = sP + (wm + g) * FSTR + ks * 8 + t;
        aq[ks][0] = __float_as_uint(p[0]);
        aq[ks][1] = __float_as_uint(p[8 * FSTR]);
        aq[ks][2] = __float_as_uint(p[4]);
        aq[ks][3] = __float_as_uint(p[8 * FSTR + 4]);
    }
    __syncthreads();

    float m0 = -1e30f, m1 = -1e30f, l0 = 0.f, l1 = 0.f;
    float o[8][4];
#pragma unroll
    for (int n = 0; n < 8; ++n)
#pragma unroll
        for (int e = 0; e < 4; ++e) o[n][e] = 0.f;

    const int nkt = 2 * qt + 2;               // k tiles of 64
    kv_issue(sbase, 0, Kp, Vp, 0, tid);
    kv_issue(sbase, 1, Kp, Vp, 1, tid);

    for (int kt = 0; kt < nkt; ++kt) {
        const int cur = kt & 1;
        if (kt + 1 < nkt) cpa_wait1(); else cpa_wait0();
        __syncthreads();
        const float* K0 = sm + cur * 64 * FSTR;
        const float* V0 = sm + (2 + cur) * 64 * FSTR;

        // S = Q @ K^T
        float cs[8][4];
#pragma unroll
        for (int n = 0; n < 8; ++n)
#pragma unroll
            for (int e = 0; e < 4; ++e) cs[n][e] = 0.f;
#pragma unroll
        for (int ks = 0; ks < 8; ++ks) {
#pragma unroll
            for (int n = 0; n < 8; ++n) {
                const float* kb = K0 + (n * 8 + g) * FSTR + ks * 8 + t;
                mma_tf32(cs[n], aq[ks][0], aq[ks][1], aq[ks][2], aq[ks][3],
                         __float_as_uint(kb[0]), __float_as_uint(kb[4]));
            }
        }

        if (kt >= 2 * qt) {
            const int cbase = (kt - 2 * qt) * 64;   // col offset rel. to q-tile rows
            const int rowg = wm + g;
#pragma unroll
            for (int n = 0; n < 8; ++n) {
                int col = cbase + n * 8 + 2 * t;
                if (col     > rowg)     cs[n][0] = -1e30f;
                if (col + 1 > rowg)     cs[n][1] = -1e30f;
                if (col     > rowg + 8) cs[n][2] = -1e30f;
                if (col + 1 > rowg + 8) cs[n][3] = -1e30f;
            }
        }

        // online softmax (two rows per thread)
        float mx0 = -1e30f, mx1 = -1e30f;
#pragma unroll
        for (int n = 0; n < 8; ++n) {
            mx0 = fmaxf(mx0, fmaxf(cs[n][0], cs[n][1]));
            mx1 = fmaxf(mx1, fmaxf(cs[n][2], cs[n][3]));
        }
        mx0 = fmaxf(mx0, __shfl_xor_sync(0xffffffffu, mx0, 1));
        mx0 = fmaxf(mx0, __shfl_xor_sync(0xffffffffu, mx0, 2));
        mx1 = fmaxf(mx1, __shfl_xor_sync(0xffffffffu, mx1, 1));
        mx1 = fmaxf(mx1, __shfl_xor_sync(0xffffffffu, mx1, 2));
        float mn0 = fmaxf(m0, mx0), mn1 = fmaxf(m1, mx1);
        float a0 = exp2f(m0 - mn0), a1 = exp2f(m1 - mn1);

        float s0 = 0.f, s1 = 0.f;
#pragma unroll
        for (int n = 0; n < 8; ++n) {
            float p00 = exp2f(cs[n][0] - mn0);
            float p01 = exp2f(cs[n][1] - mn0);
            float p10 = exp2f(cs[n][2] - mn1);
            float p11 = exp2f(cs[n][3] - mn1);
            s0 += p00 + p01;
            s1 += p10 + p11;
            *(float2*)&sP[(wm + g) * FSTR + n * 8 + 2 * t] =
                make_float2(__uint_as_float(f2tf32(p00)), __uint_as_float(f2tf32(p01)));
            *(float2*)&sP[(wm + g + 8) * FSTR + n * 8 + 2 * t] =
                make_float2(__uint_as_float(f2tf32(p10)), __uint_as_float(f2tf32(p11)));
        }
        s0 += __shfl_xor_sync(0xffffffffu, s0, 1);
        s0 += __shfl_xor_sync(0xffffffffu, s0, 2);
        s1 += __shfl_xor_sync(0xffffffffu, s1, 1);
        s1 += __shfl_xor_sync(0xffffffffu, s1, 2);
        l0 = l0 * a0 + s0;
        l1 = l1 * a1 + s1;
        m0 = mn0; m1 = mn1;
#pragma unroll
        for (int n = 0; n < 8; ++n) {
            o[n][0] *= a0; o[n][1] *= a0;
            o[n][2] *= a1; o[n][3] *= a1;
        }
        __syncwarp();

        // O += P @ V
#pragma unroll
        for (int ks = 0; ks < 8; ++ks) {
            const float* pp = sP + (wm + g) * FSTR + ks * 8 + t;
            uint32_t ap0 = __float_as_uint(pp[0]);
            uint32_t ap1 = __float_as_uint(pp[8 * FSTR]);
            uint32_t ap2 = __float_as_uint(pp[4]);
            uint32_t ap3 = __float_as_uint(pp[8 * FSTR + 4]);
#pragma unroll
            for (int n = 0; n < 8; ++n) {
                const float* vb = V0 + (ks * 8 + t) * FSTR + n * 8 + g;
                mma_tf32(o[n], ap0, ap1, ap2, ap3,
                         __float_as_uint(vb[0]), __float_as_uint(vb[4 * FSTR]));
            }
        }
        __syncthreads();
        if (kt + 2 < nkt) kv_issue(sbase, cur, Kp, Vp, kt + 2, tid);
    }

    float i0 = 1.f / l0, i1 = 1.f / l1;
    float* d0 = attnout + ((size_t)(b * SEQL) + qt * 128 + wm + g) * D_MODEL + h * HD;
#pragma unroll
    for (int n = 0; n < 8; ++n) {
        int col = n * 8 + 2 * t;
        *(float2*)(d0 + col) = make_float2(
            __uint_as_float(f2tf32(o[n][0] * i0)),
            __uint_as_float(f2tf32(o[n][1] * i0)));
        *(float2*)(d0 + 8 * D_MODEL + col) = make_float2(
            __uint_as_float(f2tf32(o[n][2] * i1)),
            __uint_as_float(f2tf32(o[n][3] * i1)));
    }
}

// ---------------------------------------------------------------------------
extern "C" void kernel_launch(void* const* d_in, const int* in_sizes, int n_in,
                              void* d_out, int out_size)
{
    const float* x  = (const float*)d_in[0];
    const int*   tp = (const int*)d_in[1];
    const float* Wq = (const float*)d_in[2];
    const float* Wk = (const float*)d_in[3];
    const float* Wv = (const float*)d_in[4];
    const float* Wo = (const float*)d_in[5];
    float* out = (float*)d_out;

    float *qp, *kp, *vp, *ap, *xcp, *wcp;
    cudaGetSymbolAddress((void**)&qp, g_q);
    cudaGetSymbolAddress((void**)&kp, g_k);
    cudaGetSymbolAddress((void**)&vp, g_v);
    cudaGetSymbolAddress((void**)&ap, g_attn);
    cudaGetSymbolAddress((void**)&xcp, g_xc);
    cudaGetSymbolAddress((void**)&wcp, g_wc);

    static int inited = 0;
    if (!inited) {
        cudaFuncSetAttribute(gemm_tf32, cudaFuncAttributeMaxDynamicSharedMemorySize,
                             GEMM_SMEM);
        cudaFuncSetAttribute(flash_mma, cudaFuncAttributeMaxDynamicSharedMemorySize,
                             FLASH_SMEM);
        inited = 1;
    }

    const float* wc0 = wcp;
    const float* wc1 = wcp + (size_t)D_MODEL * D_MODEL;
    const float* wc2 = wcp + 2 * (size_t)D_MODEL * D_MODEL;
    const float* wc3 = wcp + 3 * (size_t)D_MODEL * D_MODEL;

    cvt1_kernel<<<(MTOT * D_MODEL / 4 + 255) / 256, 256>>>((const float4*)x,
                                                           (float4*)xcp,
                                                           MTOT * D_MODEL / 4);
    cvt4_kernel<<<dim3(D_MODEL * D_MODEL / 4 / 256, 4), 256>>>(
        (const float4*)Wq, (const float4*)Wk, (const float4*)Wv, (const float4*)Wo);

    gemm_tf32<<<dim3(D_MODEL / 128, MTOT / 128, 3), 256, GEMM_SMEM>>>(
        xcp, wc0, wc1, wc2, qp, kp, vp, 1, 3, 2, tp);

    flash_mma<<<dim3(SEQL / 128, BSZ * NH), 256, FLASH_SMEM>>>(ap);

    gemm_tf32<<<dim3(D_MODEL / 128, MTOT / 128, 1), 256, GEMM_SMEM>>>(
        ap, wc3, wc3, wc3, out, out, out, 0, 0, 0, tp);
}

// round 6
// speedup vs baseline: 1.8618x; 1.8618x over previous
#include <cuda_runtime.h>
#include <cuda_fp16.h>
#include <math.h>
#include <stdint.h>

#define D_MODEL 1024
#define NH 16
#define HD 64
#define BSZ 2
#define SEQL 2048
#define MTOT (BSZ*SEQL)

// scratch (allocation-free)
__device__ float g_q[(size_t)BSZ*NH*SEQL*HD];
__device__ float g_k[(size_t)BSZ*NH*SEQL*HD];
__device__ __half g_vt[(size_t)BSZ*NH*HD*SEQL];   // V transposed, fp16
__device__ float g_attn[(size_t)MTOT*D_MODEL];
__device__ float g_xc[(size_t)MTOT*D_MODEL];
__device__ float g_wc[4][(size_t)D_MODEL*D_MODEL];

// log2(e)/8 : folded into Q so softmax uses exp2
#define QSCALE 0.18033688011112042f

__device__ __forceinline__ uint32_t f2tf32(float x) {
    uint32_t r;
    asm("cvt.rna.tf32.f32 %0, %1;" : "=r"(r) : "f"(x));
    return r;
}

__device__ __forceinline__ uint32_t pf16x2(float lo, float hi) {
    uint32_t r;
    asm("cvt.rn.f16x2.f32 %0, %1, %2;" : "=r"(r) : "f"(hi), "f"(lo));
    return r;
}

__device__ __forceinline__ void mma_tf32(float* c, uint32_t a0, uint32_t a1,
                                         uint32_t a2, uint32_t a3,
                                         uint32_t b0, uint32_t b1) {
    asm volatile(
        "mma.sync.aligned.m16n8k8.row.col.f32.tf32.tf32.f32 "
        "{%0,%1,%2,%3}, {%4,%5,%6,%7}, {%8,%9}, {%0,%1,%2,%3};"
        : "+f"(c[0]), "+f"(c[1]), "+f"(c[2]), "+f"(c[3])
        : "r"(a0), "r"(a1), "r"(a2), "r"(a3), "r"(b0), "r"(b1));
}

__device__ __forceinline__ void mma_f16(float* c, uint32_t a0, uint32_t a1,
                                        uint32_t a2, uint32_t a3,
                                        uint32_t b0, uint32_t b1) {
    asm volatile(
        "mma.sync.aligned.m16n8k16.row.col.f32.f16.f16.f32 "
        "{%0,%1,%2,%3}, {%4,%5,%6,%7}, {%8,%9}, {%0,%1,%2,%3};"
        : "+f"(c[0]), "+f"(c[1]), "+f"(c[2]), "+f"(c[3])
        : "r"(a0), "r"(a1), "r"(a2), "r"(a3), "r"(b0), "r"(b1));
}

__device__ __forceinline__ void cpa16(uint32_t dst, const void* src) {
    asm volatile("cp.async.cg.shared.global [%0], [%1], 16;" :: "r"(dst), "l"(src));
}
__device__ __forceinline__ void cpa_commit() { asm volatile("cp.async.commit_group;"); }
__device__ __forceinline__ void cpa_wait1()  { asm volatile("cp.async.wait_group 1;"); }
__device__ __forceinline__ void cpa_wait0()  { asm volatile("cp.async.wait_group 0;"); }

// ---------------------------------------------------------------------------
// tf32 convert passes
// ---------------------------------------------------------------------------
__global__ void cvt1_kernel(const float4* __restrict__ src, float4* __restrict__ dst, int n4)
{
    int i = blockIdx.x * blockDim.x + threadIdx.x;
    if (i < n4) {
        float4 v = src[i];
        v.x = __uint_as_float(f2tf32(v.x));
        v.y = __uint_as_float(f2tf32(v.y));
        v.z = __uint_as_float(f2tf32(v.z));
        v.w = __uint_as_float(f2tf32(v.w));
        dst[i] = v;
    }
}

__global__ void cvt4_kernel(const float4* __restrict__ w0, const float4* __restrict__ w1,
                            const float4* __restrict__ w2, const float4* __restrict__ w3)
{
    int z = blockIdx.y;
    const float4* src = z == 0 ? w0 : z == 1 ? w1 : z == 2 ? w2 : w3;
    float4* dst = (float4*)g_wc[z];
    int i = blockIdx.x * blockDim.x + threadIdx.x;
    float4 v = src[i];
    v.x = __uint_as_float(f2tf32(v.x));
    v.y = __uint_as_float(f2tf32(v.y));
    v.z = __uint_as_float(f2tf32(v.z));
    v.w = __uint_as_float(f2tf32(v.w));
    dst[i] = v;
}

// ---------------------------------------------------------------------------
// tf32 GEMM: Y[m,n] = sum_k A[m,k] * W[n,k]  (A, W already tf32-rounded bits)
// 128x128 tile, BK=32, 256 threads, warp tile 64x32.
// mode 0: plain fp32; 1: RoPE*QSCALE + tf32 scatter (Q);
// 3: RoPE + tf32 scatter (K); 2: fp16 transposed scatter (V^T)
// ---------------------------------------------------------------------------
#define GSTR 36
#define GSTAGE 4608
#define GEMM_SMEM (2*2*GSTAGE*4)

__global__ __launch_bounds__(256)
void gemm_tf32(const float* __restrict__ A,
               const float* __restrict__ W0, const float* __restrict__ W1,
               const float* __restrict__ W2,
               float* __restrict__ o0, float* __restrict__ o1,
               __half* __restrict__ vt,
               int md0, int md1, int md2, const int* __restrict__ tokpos)
{
    extern __shared__ float sm[];
    const int z = blockIdx.z;
    const float* W = z == 0 ? W0 : z == 1 ? W1 : W2;
    float* out     = z == 0 ? o0 : o1;
    const int mode = z == 0 ? md0 : z == 1 ? md1 : md2;

    const int tid = (int)threadIdx.x;
    const int m0 = blockIdx.y * 128, n0 = blockIdx.x * 128;
    const int lane = tid & 31, wid = tid >> 5;
    const int g = lane >> 2, t = lane & 3;
    const int wm = (wid >> 2) * 64, wn = (wid & 3) * 32;

    const int c4 = (tid & 7) * 4;
    const int r0 = tid >> 3;
    uint32_t sbase = (uint32_t)__cvta_generic_to_shared(sm);

    float c[4][4][4];
#pragma unroll
    for (int i = 0; i < 4; ++i)
#pragma unroll
        for (int j = 0; j < 4; ++j)
#pragma unroll
            for (int k = 0; k < 4; ++k) c[i][j][k] = 0.f;

#define ISSUE(stage, k0)                                                         \
    {                                                                            \
        uint32_t as_ = sbase + (uint32_t)(stage) * (2 * GSTAGE * 4);             \
        uint32_t bs_ = as_ + GSTAGE * 4;                                         \
        _Pragma("unroll")                                                        \
        for (int i_ = 0; i_ < 4; ++i_) {                                         \
            int row_ = r0 + 32 * i_;                                             \
            cpa16(as_ + (uint32_t)(row_ * GSTR + c4) * 4,                        \
                  A + (size_t)(m0 + row_) * D_MODEL + (k0) + c4);                \
            cpa16(bs_ + (uint32_t)(row_ * GSTR + c4) * 4,                        \
                  W + (size_t)(n0 + row_) * D_MODEL + (k0) + c4);                \
        }                                                                        \
        cpa_commit();                                                            \
    }

    ISSUE(0, 0);
    ISSUE(1, 32);

    for (int kt = 0; kt < 32; ++kt) {
        cpa_wait1();
        __syncthreads();
        const float* As = sm + (kt & 1) * (2 * GSTAGE);
        const float* Bs = As + GSTAGE;

#pragma unroll
        for (int ks = 0; ks < 4; ++ks) {
            uint32_t af[4][4], bf[4][2];
#pragma unroll
            for (int mt = 0; mt < 4; ++mt) {
                const float* p = As + (wm + mt * 16 + g) * GSTR + ks * 8 + t;
                af[mt][0] = __float_as_uint(p[0]);
                af[mt][1] = __float_as_uint(p[8 * GSTR]);
                af[mt][2] = __float_as_uint(p[4]);
                af[mt][3] = __float_as_uint(p[8 * GSTR + 4]);
            }
#pragma unroll
            for (int nt = 0; nt < 4; ++nt) {
                const float* p = Bs + (wn + nt * 8 + g) * GSTR + ks * 8 + t;
                bf[nt][0] = __float_as_uint(p[0]);
                bf[nt][1] = __float_as_uint(p[4]);
            }
#pragma unroll
            for (int mt = 0; mt < 4; ++mt)
#pragma unroll
                for (int nt = 0; nt < 4; ++nt)
                    mma_tf32(c[mt][nt], af[mt][0], af[mt][1], af[mt][2], af[mt][3],
                             bf[nt][0], bf[nt][1]);
        }
        __syncthreads();
        if (kt + 2 < 32) { ISSUE(kt & 1, (kt + 2) * 32); }
        else             { cpa_commit(); }
    }

    if (mode == 0) {
#pragma unroll
        for (int mt = 0; mt < 4; ++mt) {
            int rowa = m0 + wm + mt * 16 + g;
#pragma unroll
            for (int nt = 0; nt < 4; ++nt) {
                int col = n0 + wn + nt * 8 + 2 * t;
                *(float2*)(out + (size_t)rowa * D_MODEL + col) =
                    make_float2(c[mt][nt][0], c[mt][nt][1]);
                *(float2*)(out + (size_t)(rowa + 8) * D_MODEL + col) =
                    make_float2(c[mt][nt][2], c[mt][nt][3]);
            }
        }
    } else {
#pragma unroll
        for (int mt = 0; mt < 4; ++mt) {
#pragma unroll
            for (int half = 0; half < 2; ++half) {
                int m = m0 + wm + mt * 16 + g + half * 8;
                int b = m >> 11;
                int s = m & (SEQL - 1);
                float pos = (float)tokpos[s];
#pragma unroll
                for (int nt = 0; nt < 4; ++nt) {
                    int col = n0 + wn + nt * 8 + 2 * t;   // even
                    int h = col >> 6;
                    int d = col & 63;
                    float e = c[mt][nt][half * 2 + 0];
                    float o = c[mt][nt][half * 2 + 1];
                    if (mode != 2) {
                        float fr = exp2f((float)d * (-13.287712379549449f / 64.f));
                        float cs, sn;
                        sincosf(pos * fr, &sn, &cs);
                        float re = e * cs - o * sn;
                        float ro = e * sn + o * cs;
                        if (mode == 1) { re *= QSCALE; ro *= QSCALE; }
                        size_t dst = ((size_t)(b * NH + h) * SEQL + s) * HD + d;
                        *(float2*)(out + dst) = make_float2(
                            __uint_as_float(f2tf32(re)), __uint_as_float(f2tf32(ro)));
                    } else {
                        // V^T fp16: [bh][d][s]
                        size_t dst = ((size_t)(b * NH + h) * HD + d) * SEQL + s;
                        vt[dst]        = __float2half(e);
                        vt[dst + SEQL] = __float2half(o);
                    }
                }
            }
        }
    }
}

// ---------------------------------------------------------------------------
// Flash attention. CTA: 128 threads (4 warps), QT=64, KT=64.
// QK^T: tf32 m16n8k8 (K fp32 in smem). P@V: fp16 m16n8k16 with P packed
// straight from QK C-fragments (no smem round-trip); V^T fp16 in smem.
// Q holds tf32(rope(q) * log2e/8); probs via exp2.
// ---------------------------------------------------------------------------
#define FSTR 68                          // K row stride (floats)
#define VSTR 72                          // V^T row stride (fp16)
#define KBYTES (64 * FSTR * 4)           // 17408
#define VBYTES (64 * VSTR * 2)           // 9216
#define FLASH_SMEM (2 * KBYTES + 2 * VBYTES)   // 53248

__device__ __forceinline__ void kv_issue(uint32_t sbase, int stage,
                                         const float* Kp,
                                         const __half* Vtp,
                                         int tile, int tid)
{
    uint32_t dK = sbase + (uint32_t)stage * KBYTES;
    uint32_t dV = sbase + 2 * KBYTES + (uint32_t)stage * VBYTES;
#pragma unroll
    for (int i = 0; i < 8; ++i) {
        int lin = tid + i * 128;
        int row = lin >> 4;
        int cc = (lin & 15) * 4;
        cpa16(dK + (uint32_t)(row * FSTR + cc) * 4,
              Kp + (size_t)(tile * 64 + row) * HD + cc);
    }
#pragma unroll
    for (int i = 0; i < 4; ++i) {
        int lin = tid + i * 128;
        int row = lin >> 3;                 // d row 0..63
        int cc = (lin & 7) * 8;             // 8 fp16 = 16B
        cpa16(dV + (uint32_t)(row * VSTR + cc) * 2,
              Vtp + (size_t)row * SEQL + tile * 64 + cc);
    }
    cpa_commit();
}

__global__ __launch_bounds__(128)
void flash_mma(float* __restrict__ attnout)
{
    extern __shared__ float sm[];
    uint32_t sbase = (uint32_t)__cvta_generic_to_shared(sm);

    const int qt = (int)(gridDim.x - 1 - blockIdx.x);   // heavy CTAs first
    const int bh = (int)blockIdx.y;
    const int b  = bh >> 4;
    const int h  = bh & 15;
    const int tid = (int)threadIdx.x;
    const int wid = tid >> 5, lane = tid & 31;
    const int g = lane >> 2, t = lane & 3;
    const int wm = wid * 16;

    const float* Qp = g_q + (size_t)bh * SEQL * HD;
    const float* Kp = g_k + (size_t)bh * SEQL * HD;
    const __half* Vtp = g_vt + (size_t)bh * HD * SEQL;

    // stage Q tile in the K0 buffer, pick up A-fragments into registers
#pragma unroll
    for (int i = 0; i < 8; ++i) {
        int lin = tid + i * 128;
        int row = lin >> 4;
        int cc = (lin & 15) * 4;
        *(float4*)&sm[row * FSTR + cc] =
            *(const float4*)(Qp + (size_t)(qt * 64 + row) * HD + cc);
    }
    __syncthreads();
    uint32_t aq[8][4];
#pragma unroll
    for (int ks = 0; ks < 8; ++ks) {
        const float* p = sm + (wm + g) * FSTR + ks * 8 + t;
        aq[ks][0] = __float_as_uint(p[0]);
        aq[ks][1] = __float_as_uint(p[8 * FSTR]);
        aq[ks][2] = __float_as_uint(p[4]);
        aq[ks][3] = __float_as_uint(p[8 * FSTR + 4]);
    }
    __syncthreads();

    float m0 = -1e30f, m1 = -1e30f, l0 = 0.f, l1 = 0.f;
    float o[8][4];
#pragma unroll
    for (int n = 0; n < 8; ++n)
#pragma unroll
        for (int e = 0; e < 4; ++e) o[n][e] = 0.f;

    kv_issue(sbase, 0, Kp, Vtp, 0, tid);
    if (qt > 0) kv_issue(sbase, 1, Kp, Vtp, 1, tid);

    for (int kt = 0; kt <= qt; ++kt) {
        const int cur = kt & 1;
        if (kt < qt) cpa_wait1(); else cpa_wait0();
        __syncthreads();
        const float* K0 = sm + cur * (KBYTES / 4);
        const __half* Vt =
            (const __half*)((const char*)sm + 2 * KBYTES + cur * VBYTES);

        // S = Q @ K^T  (tf32)
        float cs[8][4];
#pragma unroll
        for (int n = 0; n < 8; ++n)
#pragma unroll
            for (int e = 0; e < 4; ++e) cs[n][e] = 0.f;
#pragma unroll
        for (int ks = 0; ks < 8; ++ks) {
#pragma unroll
            for (int n = 0; n < 8; ++n) {
                const float* kb = K0 + (n * 8 + g) * FSTR + ks * 8 + t;
                mma_tf32(cs[n], aq[ks][0], aq[ks][1], aq[ks][2], aq[ks][3],
                         __float_as_uint(kb[0]), __float_as_uint(kb[4]));
            }
        }

        if (kt == qt) {
            const int rowg = wm + g;
#pragma unroll
            for (int n = 0; n < 8; ++n) {
                int col = n * 8 + 2 * t;
                if (col     > rowg)     cs[n][0] = -1e30f;
                if (col + 1 > rowg)     cs[n][1] = -1e30f;
                if (col     > rowg + 8) cs[n][2] = -1e30f;
                if (col + 1 > rowg + 8) cs[n][3] = -1e30f;
            }
        }

        // online softmax (two rows per thread)
        float mx0 = -1e30f, mx1 = -1e30f;
#pragma unroll
        for (int n = 0; n < 8; ++n) {
            mx0 = fmaxf(mx0, fmaxf(cs[n][0], cs[n][1]));
            mx1 = fmaxf(mx1, fmaxf(cs[n][2], cs[n][3]));
        }
        mx0 = fmaxf(mx0, __shfl_xor_sync(0xffffffffu, mx0, 1));
        mx0 = fmaxf(mx0, __shfl_xor_sync(0xffffffffu, mx0, 2));
        mx1 = fmaxf(mx1, __shfl_xor_sync(0xffffffffu, mx1, 1));
        mx1 = fmaxf(mx1, __shfl_xor_sync(0xffffffffu, mx1, 2));
        float mn0 = fmaxf(m0, mx0), mn1 = fmaxf(m1, mx1);
        float a0 = exp2f(m0 - mn0), a1 = exp2f(m1 - mn1);

        float s0 = 0.f, s1 = 0.f;
        uint32_t pa0[8], pa1[8];          // P fragments, f16x2
#pragma unroll
        for (int n = 0; n < 8; ++n) {
            float p00 = exp2f(cs[n][0] - mn0);
            float p01 = exp2f(cs[n][1] - mn0);
            float p10 = exp2f(cs[n][2] - mn1);
            float p11 = exp2f(cs[n][3] - mn1);
            s0 += p00 + p01;
            s1 += p10 + p11;
            pa0[n] = pf16x2(p00, p01);
            pa1[n] = pf16x2(p10, p11);
        }
        s0 += __shfl_xor_sync(0xffffffffu, s0, 1);
        s0 += __shfl_xor_sync(0xffffffffu, s0, 2);
        s1 += __shfl_xor_sync(0xffffffffu, s1, 1);
        s1 += __shfl_xor_sync(0xffffffffu, s1, 2);
        l0 = l0 * a0 + s0;
        l1 = l1 * a1 + s1;
        m0 = mn0; m1 = mn1;
#pragma unroll
        for (int n = 0; n < 8; ++n) {
            o[n][0] *= a0; o[n][1] *= a0;
            o[n][2] *= a1; o[n][3] *= a1;
        }

        // O += P @ V   (fp16 m16n8k16, P straight from registers)
#pragma unroll
        for (int ks = 0; ks < 4; ++ks) {
            uint32_t a0r = pa0[2 * ks],     a1r = pa1[2 * ks];
            uint32_t a2r = pa0[2 * ks + 1], a3r = pa1[2 * ks + 1];
#pragma unroll
            for (int n = 0; n < 8; ++n) {
                const __half* vb = Vt + (n * 8 + g) * VSTR + ks * 16 + 2 * t;
                uint32_t b0 = *(const uint32_t*)vb;
                uint32_t b1 = *(const uint32_t*)(vb + 8);
                mma_f16(o[n], a0r, a1r, a2r, a3r, b0, b1);
            }
        }
        __syncthreads();
        if (kt + 2 <= qt) kv_issue(sbase, cur, Kp, Vtp, kt + 2, tid);
    }

    float i0 = 1.f / l0, i1 = 1.f / l1;
    float* d0 = attnout + ((size_t)(b * SEQL) + qt * 64 + wm + g) * D_MODEL + h * HD;
#pragma unroll
    for (int n = 0; n < 8; ++n) {
        int col = n * 8 + 2 * t;
        *(float2*)(d0 + col) = make_float2(
            __uint_as_float(f2tf32(o[n][0] * i0)),
            __uint_as_float(f2tf32(o[n][1] * i0)));
        *(float2*)(d0 + 8 * D_MODEL + col) = make_float2(
            __uint_as_float(f2tf32(o[n][2] * i1)),
            __uint_as_float(f2tf32(o[n][3] * i1)));
    }
}

// ---------------------------------------------------------------------------
extern "C" void kernel_launch(void* const* d_in, const int* in_sizes, int n_in,
                              void* d_out, int out_size)
{
    const float* x  = (const float*)d_in[0];
    const int*   tp = (const int*)d_in[1];
    const float* Wq = (const float*)d_in[2];
    const float* Wk = (const float*)d_in[3];
    const float* Wv = (const float*)d_in[4];
    const float* Wo = (const float*)d_in[5];
    float* out = (float*)d_out;

    float *qp, *kp, *ap, *xcp, *wcp;
    __half* vtp;
    cudaGetSymbolAddress((void**)&qp, g_q);
    cudaGetSymbolAddress((void**)&kp, g_k);
    cudaGetSymbolAddress((void**)&vtp, g_vt);
    cudaGetSymbolAddress((void**)&ap, g_attn);
    cudaGetSymbolAddress((void**)&xcp, g_xc);
    cudaGetSymbolAddress((void**)&wcp, g_wc);

    static int inited = 0;
    if (!inited) {
        cudaFuncSetAttribute(gemm_tf32, cudaFuncAttributeMaxDynamicSharedMemorySize,
                             GEMM_SMEM);
        cudaFuncSetAttribute(flash_mma, cudaFuncAttributeMaxDynamicSharedMemorySize,
                             FLASH_SMEM);
        inited = 1;
    }

    const float* wc0 = wcp;
    const float* wc1 = wcp + (size_t)D_MODEL * D_MODEL;
    const float* wc2 = wcp + 2 * (size_t)D_MODEL * D_MODEL;
    const float* wc3 = wcp + 3 * (size_t)D_MODEL * D_MODEL;

    cvt1_kernel<<<(MTOT * D_MODEL / 4 + 255) / 256, 256>>>((const float4*)x,
                                                           (float4*)xcp,
                                                           MTOT * D_MODEL / 4);
    cvt4_kernel<<<dim3(D_MODEL * D_MODEL / 4 / 256, 4), 256>>>(
        (const float4*)Wq, (const float4*)Wk, (const float4*)Wv, (const float4*)Wo);

    // fused QKV projection (+RoPE, Q scale; V -> transposed fp16)
    gemm_tf32<<<dim3(D_MODEL / 128, MTOT / 128, 3), 256, GEMM_SMEM>>>(
        xcp, wc0, wc1, wc2, qp, kp, vtp, 1, 3, 2, tp);

    flash_mma<<<dim3(SEQL / 64, BSZ * NH), 128, FLASH_SMEM>>>(ap);

    // output projection (fp32 result)
    gemm_tf32<<<dim3(D_MODEL / 128, MTOT / 128, 1), 256, GEMM_SMEM>>>(
        ap, wc3, wc3, wc3, out, out, vtp, 0, 0, 0, tp);
}

// round 7
// speedup vs baseline: 2.9551x; 1.5872x over previous
#include <cuda_runtime.h>
#include <cuda_fp16.h>
#include <math.h>
#include <stdint.h>

#define D_MODEL 1024
#define NH 16
#define HD 64
#define BSZ 2
#define SEQL 2048
#define MTOT (BSZ*SEQL)

// scratch (allocation-free) — fp16 pipeline
__device__ __half g_x16[(size_t)MTOT*D_MODEL];
__device__ __half g_w16[4][(size_t)D_MODEL*D_MODEL];
__device__ __half g_q16[(size_t)BSZ*NH*SEQL*HD];
__device__ __half g_k16[(size_t)BSZ*NH*SEQL*HD];
__device__ __half g_vt[(size_t)BSZ*NH*HD*SEQL];      // V transposed [bh][d][s]
__device__ __half g_attn16[(size_t)MTOT*D_MODEL];

// log2(e)/8 : folded into Q so softmax uses exp2
#define QSCALE 0.18033688011112042f

__device__ __forceinline__ uint32_t pf16x2(float lo, float hi) {
    uint32_t r;
    asm("cvt.rn.f16x2.f32 %0, %1, %2;" : "=r"(r) : "f"(hi), "f"(lo));
    return r;
}

__device__ __forceinline__ void mma_f16(float* c, uint32_t a0, uint32_t a1,
                                        uint32_t a2, uint32_t a3,
                                        uint32_t b0, uint32_t b1) {
    asm volatile(
        "mma.sync.aligned.m16n8k16.row.col.f32.f16.f16.f32 "
        "{%0,%1,%2,%3}, {%4,%5,%6,%7}, {%8,%9}, {%0,%1,%2,%3};"
        : "+f"(c[0]), "+f"(c[1]), "+f"(c[2]), "+f"(c[3])
        : "r"(a0), "r"(a1), "r"(a2), "r"(a3), "r"(b0), "r"(b1));
}

__device__ __forceinline__ void cpa16(uint32_t dst, const void* src) {
    asm volatile("cp.async.cg.shared.global [%0], [%1], 16;" :: "r"(dst), "l"(src));
}
__device__ __forceinline__ void cpa_commit() { asm volatile("cp.async.commit_group;"); }
__device__ __forceinline__ void cpa_wait1()  { asm volatile("cp.async.wait_group 1;"); }
__device__ __forceinline__ void cpa_wait0()  { asm volatile("cp.async.wait_group 0;"); }

// ---------------------------------------------------------------------------
// fp32 -> fp16 convert passes (16B-store granularity)
// ---------------------------------------------------------------------------
__global__ void cvt1_kernel(const float4* __restrict__ src, uint4* __restrict__ dst, int n8)
{
    int i = blockIdx.x * blockDim.x + threadIdx.x;
    if (i < n8) {
        float4 a = src[2 * i], b = src[2 * i + 1];
        uint4 o;
        o.x = pf16x2(a.x, a.y); o.y = pf16x2(a.z, a.w);
        o.z = pf16x2(b.x, b.y); o.w = pf16x2(b.z, b.w);
        dst[i] = o;
    }
}

__global__ void cvt4_kernel(const float4* __restrict__ w0, const float4* __restrict__ w1,
                            const float4* __restrict__ w2, const float4* __restrict__ w3)
{
    int z = blockIdx.y;
    const float4* src = z == 0 ? w0 : z == 1 ? w1 : z == 2 ? w2 : w3;
    uint4* dst = (uint4*)g_w16[z];
    int i = blockIdx.x * blockDim.x + threadIdx.x;
    float4 a = src[2 * i], b = src[2 * i + 1];
    uint4 o;
    o.x = pf16x2(a.x, a.y); o.y = pf16x2(a.z, a.w);
    o.z = pf16x2(b.x, b.y); o.w = pf16x2(b.z, b.w);
    dst[i] = o;
}

// ---------------------------------------------------------------------------
// fp16 GEMM: Y[m,n] = sum_k A[m,k] * W[n,k]   (A, W fp16; accum fp32)
// 128x128 tile, BK=32, 256 threads, warp tile 64x32, m16n8k16.
// mode 0: plain fp32 write; 1: RoPE*QSCALE -> fp16 scatter (Q);
// 3: RoPE -> fp16 scatter (K); 2: fp16 transposed scatter (V^T)
// ---------------------------------------------------------------------------
#define GSTR 40                         // fp16 units per row (80B, conflict-free)
#define GSTAGE (128*GSTR)               // fp16 per A (or B) buffer
#define GEMM_SMEM (2*2*GSTAGE*2)        // 40960 B

__global__ __launch_bounds__(256)
void gemm_f16(const __half* __restrict__ A,
              const __half* __restrict__ W0, const __half* __restrict__ W1,
              const __half* __restrict__ W2,
              float* __restrict__ o0,
              __half* __restrict__ h0, __half* __restrict__ h1,
              __half* __restrict__ vt,
              int md0, int md1, int md2, const int* __restrict__ tokpos)
{
    extern __shared__ __half smh[];
    const int z = blockIdx.z;
    const __half* W = z == 0 ? W0 : z == 1 ? W1 : W2;
    const int mode = z == 0 ? md0 : z == 1 ? md1 : md2;
    __half* outh    = z == 0 ? h0 : h1;

    const int tid = (int)threadIdx.x;
    const int m0 = blockIdx.y * 128, n0 = blockIdx.x * 128;
    const int lane = tid & 31, wid = tid >> 5;
    const int g = lane >> 2, t = lane & 3;
    const int wm = (wid >> 2) * 64, wn = (wid & 3) * 32;

    uint32_t sbase = (uint32_t)__cvta_generic_to_shared(smh);

    float c[4][4][4];
#pragma unroll
    for (int i = 0; i < 4; ++i)
#pragma unroll
        for (int j = 0; j < 4; ++j)
#pragma unroll
            for (int k = 0; k < 4; ++k) c[i][j][k] = 0.f;

    // one stage = A(128x32) + B(128x32) fp16
#define ISSUE(stage, k0)                                                         \
    {                                                                            \
        uint32_t as_ = sbase + (uint32_t)(stage) * (2 * GSTAGE * 2);             \
        uint32_t bs_ = as_ + GSTAGE * 2;                                         \
        _Pragma("unroll")                                                        \
        for (int i_ = 0; i_ < 2; ++i_) {                                         \
            int lin_ = tid + i_ * 256;                                           \
            int row_ = lin_ >> 2;                                                \
            int cc_ = (lin_ & 3) * 8;                                            \
            cpa16(as_ + (uint32_t)(row_ * GSTR + cc_) * 2,                       \
                  A + (size_t)(m0 + row_) * D_MODEL + (k0) + cc_);               \
            cpa16(bs_ + (uint32_t)(row_ * GSTR + cc_) * 2,                       \
                  W + (size_t)(n0 + row_) * D_MODEL + (k0) + cc_);               \
        }                                                                        \
        cpa_commit();                                                            \
    }

    ISSUE(0, 0);
    ISSUE(1, 32);

    for (int kt = 0; kt < 32; ++kt) {
        cpa_wait1();
        __syncthreads();
        const __half* As = smh + (kt & 1) * (2 * GSTAGE);
        const __half* Bs = As + GSTAGE;

#pragma unroll
        for (int ks = 0; ks < 2; ++ks) {
            uint32_t af[4][4], bf[4][2];
#pragma unroll
            for (int mt = 0; mt < 4; ++mt) {
                const __half* p = As + (wm + mt * 16 + g) * GSTR + ks * 16 + 2 * t;
                af[mt][0] = *(const uint32_t*)p;
                af[mt][1] = *(const uint32_t*)(p + 8 * GSTR);
                af[mt][2] = *(const uint32_t*)(p + 8);
                af[mt][3] = *(const uint32_t*)(p + 8 * GSTR + 8);
            }
#pragma unroll
            for (int nt = 0; nt < 4; ++nt) {
                const __half* p = Bs + (wn + nt * 8 + g) * GSTR + ks * 16 + 2 * t;
                bf[nt][0] = *(const uint32_t*)p;
                bf[nt][1] = *(const uint32_t*)(p + 8);
            }
#pragma unroll
            for (int mt = 0; mt < 4; ++mt)
#pragma unroll
                for (int nt = 0; nt < 4; ++nt)
                    mma_f16(c[mt][nt], af[mt][0], af[mt][1], af[mt][2], af[mt][3],
                            bf[nt][0], bf[nt][1]);
        }
        __syncthreads();
        if (kt + 2 < 32) { ISSUE(kt & 1, (kt + 2) * 32); }
        else             { cpa_commit(); }
    }

    if (mode == 0) {
#pragma unroll
        for (int mt = 0; mt < 4; ++mt) {
            int rowa = m0 + wm + mt * 16 + g;
#pragma unroll
            for (int nt = 0; nt < 4; ++nt) {
                int col = n0 + wn + nt * 8 + 2 * t;
                *(float2*)(o0 + (size_t)rowa * D_MODEL + col) =
                    make_float2(c[mt][nt][0], c[mt][nt][1]);
                *(float2*)(o0 + (size_t)(rowa + 8) * D_MODEL + col) =
                    make_float2(c[mt][nt][2], c[mt][nt][3]);
            }
        }
    } else {
#pragma unroll
        for (int mt = 0; mt < 4; ++mt) {
#pragma unroll
            for (int half = 0; half < 2; ++half) {
                int m = m0 + wm + mt * 16 + g + half * 8;
                int b = m >> 11;
                int s = m & (SEQL - 1);
                float pos = (float)tokpos[s];
#pragma unroll
                for (int nt = 0; nt < 4; ++nt) {
                    int col = n0 + wn + nt * 8 + 2 * t;   // even
                    int h = col >> 6;
                    int d = col & 63;
                    float e = c[mt][nt][half * 2 + 0];
                    float o = c[mt][nt][half * 2 + 1];
                    if (mode != 2) {
                        float fr = exp2f((float)d * (-13.287712379549449f / 64.f));
                        float cs, sn;
                        sincosf(pos * fr, &sn, &cs);
                        float re = e * cs - o * sn;
                        float ro = e * sn + o * cs;
                        if (mode == 1) { re *= QSCALE; ro *= QSCALE; }
                        size_t dst = ((size_t)(b * NH + h) * SEQL + s) * HD + d;
                        *(uint32_t*)(outh + dst) = pf16x2(re, ro);
                    } else {
                        // V^T fp16: [bh][d][s]
                        size_t dst = ((size_t)(b * NH + h) * HD + d) * SEQL + s;
                        vt[dst]        = __float2half(e);
                        vt[dst + SEQL] = __float2half(o);
                    }
                }
            }
        }
    }
}

// ---------------------------------------------------------------------------
// Flash attention, all-fp16 mma. CTA: 128 threads (4 warps), QT=64, KT=64.
// QK^T: fp16 m16n8k16 (K fp16 in smem, Q frags in regs). P@V: fp16 with P
// packed straight from C-fragments; V^T fp16 in smem. Output fp16.
// Q holds fp16(rope(q) * log2e/8); probs via exp2.
// ---------------------------------------------------------------------------
#define FSTR 72                          // fp16 units per row (144B, conflict-free)
#define KBYTES (64 * FSTR * 2)           // 9216
#define VBYTES (64 * FSTR * 2)           // 9216
#define FLASH_SMEM (2 * KBYTES + 2 * VBYTES)   // 36864

__device__ __forceinline__ void kv_issue(uint32_t sbase, int stage,
                                         const __half* Kp,
                                         const __half* Vtp,
                                         int tile, int tid)
{
    uint32_t dK = sbase + (uint32_t)stage * KBYTES;
    uint32_t dV = sbase + 2 * KBYTES + (uint32_t)stage * VBYTES;
#pragma unroll
    for (int i = 0; i < 4; ++i) {
        int lin = tid + i * 128;
        int row = lin >> 3;                 // 0..63
        int cc = (lin & 7) * 8;             // 8 fp16 = 16B
        cpa16(dK + (uint32_t)(row * FSTR + cc) * 2,
              Kp + (size_t)(tile * 64 + row) * HD + cc);
        cpa16(dV + (uint32_t)(row * FSTR + cc) * 2,
              Vtp + (size_t)row * SEQL + tile * 64 + cc);
    }
    cpa_commit();
}

__global__ __launch_bounds__(128)
void flash_mma(__half* __restrict__ attnout)
{
    extern __shared__ __half smh[];
    uint32_t sbase = (uint32_t)__cvta_generic_to_shared(smh);

    const int qt = (int)(gridDim.x - 1 - blockIdx.x);   // heavy CTAs first
    const int bh = (int)blockIdx.y;
    const int b  = bh >> 4;
    const int h  = bh & 15;
    const int tid = (int)threadIdx.x;
    const int wid = tid >> 5, lane = tid & 31;
    const int g = lane >> 2, t = lane & 3;
    const int wm = wid * 16;

    const __half* Qp = g_q16 + (size_t)bh * SEQL * HD;
    const __half* Kp = g_k16 + (size_t)bh * SEQL * HD;
    const __half* Vtp = g_vt + (size_t)bh * HD * SEQL;

    // stage Q tile (64x64 fp16) in the K0 buffer, pick up A-fragments
#pragma unroll
    for (int i = 0; i < 4; ++i) {
        int lin = tid + i * 128;
        int row = lin >> 3;
        int cc = (lin & 7) * 8;
        *(uint4*)&smh[row * FSTR + cc] =
            *(const uint4*)(Qp + (size_t)(qt * 64 + row) * HD + cc);
    }
    __syncthreads();
    uint32_t aq[4][4];
#pragma unroll
    for (int ks = 0; ks < 4; ++ks) {
        const __half* p = smh + (wm + g) * FSTR + ks * 16 + 2 * t;
        aq[ks][0] = *(const uint32_t*)p;
        aq[ks][1] = *(const uint32_t*)(p + 8 * FSTR);
        aq[ks][2] = *(const uint32_t*)(p + 8);
        aq[ks][3] = *(const uint32_t*)(p + 8 * FSTR + 8);
    }
    __syncthreads();

    float m0 = -1e30f, m1 = -1e30f, l0 = 0.f, l1 = 0.f;
    float o[8][4];
#pragma unroll
    for (int n = 0; n < 8; ++n)
#pragma unroll
        for (int e = 0; e < 4; ++e) o[n][e] = 0.f;

    kv_issue(sbase, 0, Kp, Vtp, 0, tid);
    if (qt > 0) kv_issue(sbase, 1, Kp, Vtp, 1, tid);

    for (int kt = 0; kt <= qt; ++kt) {
        const int cur = kt & 1;
        if (kt < qt) cpa_wait1(); else cpa_wait0();
        __syncthreads();
        const __half* K0 = smh + cur * (KBYTES / 2);
        const __half* Vt = smh + (2 * KBYTES + cur * VBYTES) / 2;

        // S = Q @ K^T  (fp16, fp32 accum)
        float cs[8][4];
#pragma unroll
        for (int n = 0; n < 8; ++n)
#pragma unroll
            for (int e = 0; e < 4; ++e) cs[n][e] = 0.f;
#pragma unroll
        for (int ks = 0; ks < 4; ++ks) {
#pragma unroll
            for (int n = 0; n < 8; ++n) {
                const __half* kb = K0 + (n * 8 + g) * FSTR + ks * 16 + 2 * t;
                mma_f16(cs[n], aq[ks][0], aq[ks][1], aq[ks][2], aq[ks][3],
                        *(const uint32_t*)kb, *(const uint32_t*)(kb + 8));
            }
        }

        if (kt == qt) {
            const int rowg = wm + g;
#pragma unroll
            for (int n = 0; n < 8; ++n) {
                int col = n * 8 + 2 * t;
                if (col     > rowg)     cs[n][0] = -1e30f;
                if (col + 1 > rowg)     cs[n][1] = -1e30f;
                if (col     > rowg + 8) cs[n][2] = -1e30f;
                if (col + 1 > rowg + 8) cs[n][3] = -1e30f;
            }
        }

        // online softmax (two rows per thread)
        float mx0 = -1e30f, mx1 = -1e30f;
#pragma unroll
        for (int n = 0; n < 8; ++n) {
            mx0 = fmaxf(mx0, fmaxf(cs[n][0], cs[n][1]));
            mx1 = fmaxf(mx1, fmaxf(cs[n][2], cs[n][3]));
        }
        mx0 = fmaxf(mx0, __shfl_xor_sync(0xffffffffu, mx0, 1));
        mx0 = fmaxf(mx0, __shfl_xor_sync(0xffffffffu, mx0, 2));
        mx1 = fmaxf(mx1, __shfl_xor_sync(0xffffffffu, mx1, 1));
        mx1 = fmaxf(mx1, __shfl_xor_sync(0xffffffffu, mx1, 2));
        float mn0 = fmaxf(m0, mx0), mn1 = fmaxf(m1, mx1);
        float a0 = exp2f(m0 - mn0), a1 = exp2f(m1 - mn1);

        float s0 = 0.f, s1 = 0.f;
        uint32_t pa0[8], pa1[8];          // P fragments, f16x2
#pragma unroll
        for (int n = 0; n < 8; ++n) {
            float p00 = exp2f(cs[n][0] - mn0);
            float p01 = exp2f(cs[n][1] - mn0);
            float p10 = exp2f(cs[n][2] - mn1);
            float p11 = exp2f(cs[n][3] - mn1);
            s0 += p00 + p01;
            s1 += p10 + p11;
            pa0[n] = pf16x2(p00, p01);
            pa1[n] = pf16x2(p10, p11);
        }
        s0 += __shfl_xor_sync(0xffffffffu, s0, 1);
        s0 += __shfl_xor_sync(0xffffffffu, s0, 2);
        s1 += __shfl_xor_sync(0xffffffffu, s1, 1);
        s1 += __shfl_xor_sync(0xffffffffu, s1, 2);
        l0 = l0 * a0 + s0;
        l1 = l1 * a1 + s1;
        m0 = mn0; m1 = mn1;
#pragma unroll
        for (int n = 0; n < 8; ++n) {
            o[n][0] *= a0; o[n][1] *= a0;
            o[n][2] *= a1; o[n][3] *= a1;
        }

        // O += P @ V   (fp16, P straight from registers)
#pragma unroll
        for (int ks = 0; ks < 4; ++ks) {
            uint32_t a0r = pa0[2 * ks],     a1r = pa1[2 * ks];
            uint32_t a2r = pa0[2 * ks + 1], a3r = pa1[2 * ks + 1];
#pragma unroll
            for (int n = 0; n < 8; ++n) {
                const __half* vb = Vt + (n * 8 + g) * FSTR + ks * 16 + 2 * t;
                mma_f16(o[n], a0r, a1r, a2r, a3r,
                        *(const uint32_t*)vb, *(const uint32_t*)(vb + 8));
            }
        }
        __syncthreads();
        if (kt + 2 <= qt) kv_issue(sbase, cur, Kp, Vtp, kt + 2, tid);
    }

    float i0 = 1.f / l0, i1 = 1.f / l1;
    __half* d0 = attnout + ((size_t)(b * SEQL) + qt * 64 + wm + g) * D_MODEL + h * HD;
#pragma unroll
    for (int n = 0; n < 8; ++n) {
        int col = n * 8 + 2 * t;
        *(uint32_t*)(d0 + col) = pf16x2(o[n][0] * i0, o[n][1] * i0);
        *(uint32_t*)(d0 + 8 * D_MODEL + col) = pf16x2(o[n][2] * i1, o[n][3] * i1);
    }
}

// ---------------------------------------------------------------------------
extern "C" void kernel_launch(void* const* d_in, const int* in_sizes, int n_in,
                              void* d_out, int out_size)
{
    const float* x  = (const float*)d_in[0];
    const int*   tp = (const int*)d_in[1];
    const float* Wq = (const float*)d_in[2];
    const float* Wk = (const float*)d_in[3];
    const float* Wv = (const float*)d_in[4];
    const float* Wo = (const float*)d_in[5];
    float* out = (float*)d_out;

    __half *x16p, *w16p, *q16p, *k16p, *vtp, *a16p;
    cudaGetSymbolAddress((void**)&x16p, g_x16);
    cudaGetSymbolAddress((void**)&w16p, g_w16);
    cudaGetSymbolAddress((void**)&q16p, g_q16);
    cudaGetSymbolAddress((void**)&k16p, g_k16);
    cudaGetSymbolAddress((void**)&vtp, g_vt);
    cudaGetSymbolAddress((void**)&a16p, g_attn16);

    static int inited = 0;
    if (!inited) {
        cudaFuncSetAttribute(gemm_f16, cudaFuncAttributeMaxDynamicSharedMemorySize,
                             GEMM_SMEM);
        cudaFuncSetAttribute(flash_mma, cudaFuncAttributeMaxDynamicSharedMemorySize,
                             FLASH_SMEM);
        inited = 1;
    }

    const __half* w0 = w16p;
    const __half* w1 = w16p + (size_t)D_MODEL * D_MODEL;
    const __half* w2 = w16p + 2 * (size_t)D_MODEL * D_MODEL;
    const __half* w3 = w16p + 3 * (size_t)D_MODEL * D_MODEL;

    cvt1_kernel<<<(MTOT * D_MODEL / 8 + 255) / 256, 256>>>((const float4*)x,
                                                           (uint4*)x16p,
                                                           MTOT * D_MODEL / 8);
    cvt4_kernel<<<dim3(D_MODEL * D_MODEL / 8 / 256, 4), 256>>>(
        (const float4*)Wq, (const float4*)Wk, (const float4*)Wv, (const float4*)Wo);

    // fused QKV projection (+RoPE, Q scale; all outputs fp16; V transposed)
    gemm_f16<<<dim3(D_MODEL / 128, MTOT / 128, 3), 256, GEMM_SMEM>>>(
        x16p, w0, w1, w2, out, q16p, k16p, vtp, 1, 3, 2, tp);

    flash_mma<<<dim3(SEQL / 64, BSZ * NH), 128, FLASH_SMEM>>>(a16p);

    // output projection (fp32 result)
    gemm_f16<<<dim3(D_MODEL / 128, MTOT / 128, 1), 256, GEMM_SMEM>>>(
        a16p, w3, w3, w3, out, q16p, k16p, vtp, 0, 0, 0, tp);
}

// round 8
// speedup vs baseline: 2.9883x; 1.0112x over previous
#include <cuda_runtime.h>
#include <cuda_fp16.h>
#include <math.h>
#include <stdint.h>

#define D_MODEL 1024
#define NH 16
#define HD 64
#define BSZ 2
#define SEQL 2048
#define MTOT (BSZ*SEQL)

// scratch (allocation-free) — fp16 pipeline
__device__ __half g_x16[(size_t)MTOT*D_MODEL];
__device__ __half g_w16[4][(size_t)D_MODEL*D_MODEL];
__device__ __half g_q16[(size_t)BSZ*NH*SEQL*HD];
__device__ __half g_k16[(size_t)BSZ*NH*SEQL*HD];
__device__ __half g_vt[(size_t)BSZ*NH*HD*SEQL];      // V transposed [bh][d][s]
__device__ __half g_attn16[(size_t)MTOT*D_MODEL];

// log2(e)/8 : folded into Q so softmax uses exp2
#define QSCALE 0.18033688011112042f

__device__ __forceinline__ uint32_t pf16x2(float lo, float hi) {
    uint32_t r;
    asm("cvt.rn.f16x2.f32 %0, %1, %2;" : "=r"(r) : "f"(hi), "f"(lo));
    return r;
}

__device__ __forceinline__ void mma_f16(float* c, uint32_t a0, uint32_t a1,
                                        uint32_t a2, uint32_t a3,
                                        uint32_t b0, uint32_t b1) {
    asm volatile(
        "mma.sync.aligned.m16n8k16.row.col.f32.f16.f16.f32 "
        "{%0,%1,%2,%3}, {%4,%5,%6,%7}, {%8,%9}, {%0,%1,%2,%3};"
        : "+f"(c[0]), "+f"(c[1]), "+f"(c[2]), "+f"(c[3])
        : "r"(a0), "r"(a1), "r"(a2), "r"(a3), "r"(b0), "r"(b1));
}

__device__ __forceinline__ void ldm4(uint32_t* r, uint32_t addr) {
    asm volatile("ldmatrix.sync.aligned.m8n8.x4.shared.b16 {%0,%1,%2,%3}, [%4];"
                 : "=r"(r[0]), "=r"(r[1]), "=r"(r[2]), "=r"(r[3]) : "r"(addr));
}

__device__ __forceinline__ void cpa16(uint32_t dst, const void* src) {
    asm volatile("cp.async.cg.shared.global [%0], [%1], 16;" :: "r"(dst), "l"(src));
}
__device__ __forceinline__ void cpa_commit() { asm volatile("cp.async.commit_group;"); }
__device__ __forceinline__ void cpa_wait2()  { asm volatile("cp.async.wait_group 2;"); }
__device__ __forceinline__ void cpa_wait1()  { asm volatile("cp.async.wait_group 1;"); }
__device__ __forceinline__ void cpa_wait0()  { asm volatile("cp.async.wait_group 0;"); }

// ---------------------------------------------------------------------------
// fp32 -> fp16 convert passes (16B-store granularity)
// ---------------------------------------------------------------------------
__global__ void cvt1_kernel(const float4* __restrict__ src, uint4* __restrict__ dst, int n8)
{
    int i = blockIdx.x * blockDim.x + threadIdx.x;
    if (i < n8) {
        float4 a = src[2 * i], b = src[2 * i + 1];
        uint4 o;
        o.x = pf16x2(a.x, a.y); o.y = pf16x2(a.z, a.w);
        o.z = pf16x2(b.x, b.y); o.w = pf16x2(b.z, b.w);
        dst[i] = o;
    }
}

__global__ void cvt4_kernel(const float4* __restrict__ w0, const float4* __restrict__ w1,
                            const float4* __restrict__ w2, const float4* __restrict__ w3)
{
    int z = blockIdx.y;
    const float4* src = z == 0 ? w0 : z == 1 ? w1 : z == 2 ? w2 : w3;
    uint4* dst = (uint4*)g_w16[z];
    int i = blockIdx.x * blockDim.x + threadIdx.x;
    float4 a = src[2 * i], b = src[2 * i + 1];
    uint4 o;
    o.x = pf16x2(a.x, a.y); o.y = pf16x2(a.z, a.w);
    o.z = pf16x2(b.x, b.y); o.w = pf16x2(b.z, b.w);
    dst[i] = o;
}

// ---------------------------------------------------------------------------
// fp16 GEMM: Y[m,n] = sum_k A[m,k] * W[n,k]
// CTA tile 128x128, BK=32, 128 threads (4 warps), warp tile 64x64.
// ldmatrix.x4 fragment loads, 3-stage cp.async pipeline.
// mode 0: plain fp32 write; 1: RoPE*QSCALE -> fp16 scatter (Q);
// 3: RoPE -> fp16 scatter (K); 2: fp16 transposed scatter (V^T)
// ---------------------------------------------------------------------------
#define GSTR 40                          // fp16 units per row (80B, conflict-free)
#define GST (128*GSTR)                   // halves per (A or B) tile buffer
#define GEMM_SMEM (3*2*GST*2)            // 61440 B

__global__ __launch_bounds__(128)
void gemm_f16(const __half* __restrict__ A,
              const __half* __restrict__ W0, const __half* __restrict__ W1,
              const __half* __restrict__ W2,
              float* __restrict__ o0,
              __half* __restrict__ h0, __half* __restrict__ h1,
              __half* __restrict__ vt,
              int md0, int md1, int md2, const int* __restrict__ tokpos)
{
    extern __shared__ __half smh[];
    const int z = blockIdx.z;
    const __half* W = z == 0 ? W0 : z == 1 ? W1 : W2;
    const int mode = z == 0 ? md0 : z == 1 ? md1 : md2;
    __half* outh    = z == 0 ? h0 : h1;

    const int tid = (int)threadIdx.x;
    const int m0 = blockIdx.y * 128, n0 = blockIdx.x * 128;
    const int lane = tid & 31, wid = tid >> 5;
    const int g = lane >> 2, t = lane & 3;
    const int wm = (wid >> 1) * 64, wn = (wid & 1) * 64;

    uint32_t sbase = (uint32_t)__cvta_generic_to_shared(smh);

    // per-lane ldmatrix offsets (halves, within a tile buffer)
    const int aoff = (wm + (lane & 15)) * GSTR + (lane >> 4) * 8;
    const int boff = (wn + (lane >> 4) * 8 + (lane & 7)) * GSTR + ((lane >> 3) & 1) * 8;

    float c[4][8][4];
#pragma unroll
    for (int i = 0; i < 4; ++i)
#pragma unroll
        for (int j = 0; j < 8; ++j)
#pragma unroll
            for (int k = 0; k < 4; ++k) c[i][j][k] = 0.f;

    // one stage = A(128x32) + B(128x32) fp16; 1024 cp.async / 128 thr = 8 each
#define ISSUE(stage, k0)                                                         \
    {                                                                            \
        uint32_t as_ = sbase + (uint32_t)(stage) * (2 * GST * 2);                \
        uint32_t bs_ = as_ + GST * 2;                                            \
        _Pragma("unroll")                                                        \
        for (int i_ = 0; i_ < 4; ++i_) {                                         \
            int lin_ = tid + i_ * 128;                                           \
            int row_ = lin_ >> 2;                                                \
            int cc_ = (lin_ & 3) * 8;                                            \
            cpa16(as_ + (uint32_t)(row_ * GSTR + cc_) * 2,                       \
                  A + (size_t)(m0 + row_) * D_MODEL + (k0) + cc_);               \
            cpa16(bs_ + (uint32_t)(row_ * GSTR + cc_) * 2,                       \
                  W + (size_t)(n0 + row_) * D_MODEL + (k0) + cc_);               \
        }                                                                        \
        cpa_commit();                                                            \
    }

    ISSUE(0, 0);
    ISSUE(1, 32);
    ISSUE(2, 64);

    int stage = 0;
    for (int kt = 0; kt < 32; ++kt) {
        cpa_wait2();
        __syncthreads();
        uint32_t abase = sbase + (uint32_t)stage * (2 * GST * 2) + (uint32_t)aoff * 2;
        uint32_t bbase = sbase + (uint32_t)stage * (2 * GST * 2) + GST * 2
                       + (uint32_t)boff * 2;

#pragma unroll
        for (int ks = 0; ks < 2; ++ks) {
            uint32_t af[4][4], bf[4][4];
#pragma unroll
            for (int mt = 0; mt < 4; ++mt)
                ldm4(af[mt], abase + (uint32_t)(mt * 16 * GSTR + ks * 16) * 2);
#pragma unroll
            for (int np = 0; np < 4; ++np)
                ldm4(bf[np], bbase + (uint32_t)(np * 16 * GSTR + ks * 16) * 2);
#pragma unroll
            for (int mt = 0; mt < 4; ++mt)
#pragma unroll
                for (int np = 0; np < 4; ++np) {
                    mma_f16(c[mt][2 * np],     af[mt][0], af[mt][1], af[mt][2],
                            af[mt][3], bf[np][0], bf[np][1]);
                    mma_f16(c[mt][2 * np + 1], af[mt][0], af[mt][1], af[mt][2],
                            af[mt][3], bf[np][2], bf[np][3]);
                }
        }
        __syncthreads();
        if (kt + 3 < 32) { ISSUE(stage, (kt + 3) * 32); }
        else             { cpa_commit(); }
        stage = stage == 2 ? 0 : stage + 1;
    }

    if (mode == 0) {
#pragma unroll
        for (int mt = 0; mt < 4; ++mt) {
            int rowa = m0 + wm + mt * 16 + g;
#pragma unroll
            for (int j = 0; j < 8; ++j) {
                int col = n0 + wn + j * 8 + 2 * t;
                *(float2*)(o0 + (size_t)rowa * D_MODEL + col) =
                    make_float2(c[mt][j][0], c[mt][j][1]);
                *(float2*)(o0 + (size_t)(rowa + 8) * D_MODEL + col) =
                    make_float2(c[mt][j][2], c[mt][j][3]);
            }
        }
    } else {
#pragma unroll
        for (int mt = 0; mt < 4; ++mt) {
#pragma unroll
            for (int half = 0; half < 2; ++half) {
                int m = m0 + wm + mt * 16 + g + half * 8;
                int b = m >> 11;
                int s = m & (SEQL - 1);
                float pos = (float)tokpos[s];
#pragma unroll
                for (int j = 0; j < 8; ++j) {
                    int col = n0 + wn + j * 8 + 2 * t;   // even
                    int h = col >> 6;
                    int d = col & 63;
                    float e = c[mt][j][half * 2 + 0];
                    float o = c[mt][j][half * 2 + 1];
                    if (mode != 2) {
                        float fr = exp2f((float)d * (-13.287712379549449f / 64.f));
                        float cs, sn;
                        sincosf(pos * fr, &sn, &cs);
                        float re = e * cs - o * sn;
                        float ro = e * sn + o * cs;
                        if (mode == 1) { re *= QSCALE; ro *= QSCALE; }
                        size_t dst = ((size_t)(b * NH + h) * SEQL + s) * HD + d;
                        *(uint32_t*)(outh + dst) = pf16x2(re, ro);
                    } else {
                        size_t dst = ((size_t)(b * NH + h) * HD + d) * SEQL + s;
                        vt[dst]        = __float2half(e);
                        vt[dst + SEQL] = __float2half(o);
                    }
                }
            }
        }
    }
}

// ---------------------------------------------------------------------------
// Flash attention, all-fp16 mma. CTA: 128 threads (4 warps), QT=64, KT=64.
// (unchanged from R7 — 88.8us)
// ---------------------------------------------------------------------------
#define FSTR 72
#define KBYTES (64 * FSTR * 2)
#define VBYTES (64 * FSTR * 2)
#define FLASH_SMEM (2 * KBYTES + 2 * VBYTES)

__device__ __forceinline__ void kv_issue(uint32_t sbase, int stage,
                                         const __half* Kp,
                                         const __half* Vtp,
                                         int tile, int tid)
{
    uint32_t dK = sbase + (uint32_t)stage * KBYTES;
    uint32_t dV = sbase + 2 * KBYTES + (uint32_t)stage * VBYTES;
#pragma unroll
    for (int i = 0; i < 4; ++i) {
        int lin = tid + i * 128;
        int row = lin >> 3;
        int cc = (lin & 7) * 8;
        cpa16(dK + (uint32_t)(row * FSTR + cc) * 2,
              Kp + (size_t)(tile * 64 + row) * HD + cc);
        cpa16(dV + (uint32_t)(row * FSTR + cc) * 2,
              Vtp + (size_t)row * SEQL + tile * 64 + cc);
    }
    cpa_commit();
}

__global__ __launch_bounds__(128)
void flash_mma(__half* __restrict__ attnout)
{
    extern __shared__ __half smh[];
    uint32_t sbase = (uint32_t)__cvta_generic_to_shared(smh);

    const int qt = (int)(gridDim.x - 1 - blockIdx.x);
    const int bh = (int)blockIdx.y;
    const int b  = bh >> 4;
    const int h  = bh & 15;
    const int tid = (int)threadIdx.x;
    const int wid = tid >> 5, lane = tid & 31;
    const int g = lane >> 2, t = lane & 3;
    const int wm = wid * 16;

    const __half* Qp = g_q16 + (size_t)bh * SEQL * HD;
    const __half* Kp = g_k16 + (size_t)bh * SEQL * HD;
    const __half* Vtp = g_vt + (size_t)bh * HD * SEQL;

#pragma unroll
    for (int i = 0; i < 4; ++i) {
        int lin = tid + i * 128;
        int row = lin >> 3;
        int cc = (lin & 7) * 8;
        *(uint4*)&smh[row * FSTR + cc] =
            *(const uint4*)(Qp + (size_t)(qt * 64 + row) * HD + cc);
    }
    __syncthreads();
    uint32_t aq[4][4];
#pragma unroll
    for (int ks = 0; ks < 4; ++ks) {
        const __half* p = smh + (wm + g) * FSTR + ks * 16 + 2 * t;
        aq[ks][0] = *(const uint32_t*)p;
        aq[ks][1] = *(const uint32_t*)(p + 8 * FSTR);
        aq[ks][2] = *(const uint32_t*)(p + 8);
        aq[ks][3] = *(const uint32_t*)(p + 8 * FSTR + 8);
    }
    __syncthreads();

    float m0 = -1e30f, m1 = -1e30f, l0 = 0.f, l1 = 0.f;
    float o[8][4];
#pragma unroll
    for (int n = 0; n < 8; ++n)
#pragma unroll
        for (int e = 0; e < 4; ++e) o[n][e] = 0.f;

    kv_issue(sbase, 0, Kp, Vtp, 0, tid);
    if (qt > 0) kv_issue(sbase, 1, Kp, Vtp, 1, tid);

    for (int kt = 0; kt <= qt; ++kt) {
        const int cur = kt & 1;
        if (kt < qt) cpa_wait1(); else cpa_wait0();
        __syncthreads();
        const __half* K0 = smh + cur * (KBYTES / 2);
        const __half* Vt = smh + (2 * KBYTES + cur * VBYTES) / 2;

        float cs[8][4];
#pragma unroll
        for (int n = 0; n < 8; ++n)
#pragma unroll
            for (int e = 0; e < 4; ++e) cs[n][e] = 0.f;
#pragma unroll
        for (int ks = 0; ks < 4; ++ks) {
#pragma unroll
            for (int n = 0; n < 8; ++n) {
                const __half* kb = K0 + (n * 8 + g) * FSTR + ks * 16 + 2 * t;
                mma_f16(cs[n], aq[ks][0], aq[ks][1], aq[ks][2], aq[ks][3],
                        *(const uint32_t*)kb, *(const uint32_t*)(kb + 8));
            }
        }

        if (kt == qt) {
            const int rowg = wm + g;
#pragma unroll
            for (int n = 0; n < 8; ++n) {
                int col = n * 8 + 2 * t;
                if (col     > rowg)     cs[n][0] = -1e30f;
                if (col + 1 > rowg)     cs[n][1] = -1e30f;
                if (col     > rowg + 8) cs[n][2] = -1e30f;
                if (col + 1 > rowg + 8) cs[n][3] = -1e30f;
            }
        }

        float mx0 = -1e30f, mx1 = -1e30f;
#pragma unroll
        for (int n = 0; n < 8; ++n) {
            mx0 = fmaxf(mx0, fmaxf(cs[n][0], cs[n][1]));
            mx1 = fmaxf(mx1, fmaxf(cs[n][2], cs[n][3]));
        }
        mx0 = fmaxf(mx0, __shfl_xor_sync(0xffffffffu, mx0, 1));
        mx0 = fmaxf(mx0, __shfl_xor_sync(0xffffffffu, mx0, 2));
        mx1 = fmaxf(mx1, __shfl_xor_sync(0xffffffffu, mx1, 1));
        mx1 = fmaxf(mx1, __shfl_xor_sync(0xffffffffu, mx1, 2));
        float mn0 = fmaxf(m0, mx0), mn1 = fmaxf(m1, mx1);
        float a0 = exp2f(m0 - mn0), a1 = exp2f(m1 - mn1);

        float s0 = 0.f, s1 = 0.f;
        uint32_t pa0[8], pa1[8];
#pragma unroll
        for (int n = 0; n < 8; ++n) {
            float p00 = exp2f(cs[n][0] - mn0);
            float p01 = exp2f(cs[n][1] - mn0);
            float p10 = exp2f(cs[n][2] - mn1);
            float p11 = exp2f(cs[n][3] - mn1);
            s0 += p00 + p01;
            s1 += p10 + p11;
            pa0[n] = pf16x2(p00, p01);
            pa1[n] = pf16x2(p10, p11);
        }
        s0 += __shfl_xor_sync(0xffffffffu, s0, 1);
        s0 += __shfl_xor_sync(0xffffffffu, s0, 2);
        s1 += __shfl_xor_sync(0xffffffffu, s1, 1);
        s1 += __shfl_xor_sync(0xffffffffu, s1, 2);
        l0 = l0 * a0 + s0;
        l1 = l1 * a1 + s1;
        m0 = mn0; m1 = mn1;
#pragma unroll
        for (int n = 0; n < 8; ++n) {
            o[n][0] *= a0; o[n][1] *= a0;
            o[n][2] *= a1; o[n][3] *= a1;
        }

#pragma unroll
        for (int ks = 0; ks < 4; ++ks) {
            uint32_t a0r = pa0[2 * ks],     a1r = pa1[2 * ks];
            uint32_t a2r = pa0[2 * ks + 1], a3r = pa1[2 * ks + 1];
#pragma unroll
            for (int n = 0; n < 8; ++n) {
                const __half* vb = Vt + (n * 8 + g) * FSTR + ks * 16 + 2 * t;
                mma_f16(o[n], a0r, a1r, a2r, a3r,
                        *(const uint32_t*)vb, *(const uint32_t*)(vb + 8));
            }
        }
        __syncthreads();
        if (kt + 2 <= qt) kv_issue(sbase, cur, Kp, Vtp, kt + 2, tid);
    }

    float i0 = 1.f / l0, i1 = 1.f / l1;
    __half* d0 = attnout + ((size_t)(b * SEQL) + qt * 64 + wm + g) * D_MODEL + h * HD;
#pragma unroll
    for (int n = 0; n < 8; ++n) {
        int col = n * 8 + 2 * t;
        *(uint32_t*)(d0 + col) = pf16x2(o[n][0] * i0, o[n][1] * i0);
        *(uint32_t*)(d0 + 8 * D_MODEL + col) = pf16x2(o[n][2] * i1, o[n][3] * i1);
    }
}

// ---------------------------------------------------------------------------
extern "C" void kernel_launch(void* const* d_in, const int* in_sizes, int n_in,
                              void* d_out, int out_size)
{
    const float* x  = (const float*)d_in[0];
    const int*   tp = (const int*)d_in[1];
    const float* Wq = (const float*)d_in[2];
    const float* Wk = (const float*)d_in[3];
    const float* Wv = (const float*)d_in[4];
    const float* Wo = (const float*)d_in[5];
    float* out = (float*)d_out;

    __half *x16p, *w16p, *q16p, *k16p, *vtp, *a16p;
    cudaGetSymbolAddress((void**)&x16p, g_x16);
    cudaGetSymbolAddress((void**)&w16p, g_w16);
    cudaGetSymbolAddress((void**)&q16p, g_q16);
    cudaGetSymbolAddress((void**)&k16p, g_k16);
    cudaGetSymbolAddress((void**)&vtp, g_vt);
    cudaGetSymbolAddress((void**)&a16p, g_attn16);

    static int inited = 0;
    if (!inited) {
        cudaFuncSetAttribute(gemm_f16, cudaFuncAttributeMaxDynamicSharedMemorySize,
                             GEMM_SMEM);
        cudaFuncSetAttribute(flash_mma, cudaFuncAttributeMaxDynamicSharedMemorySize,
                             FLASH_SMEM);
        inited = 1;
    }

    const __half* w0 = w16p;
    const __half* w1 = w16p + (size_t)D_MODEL * D_MODEL;
    const __half* w2 = w16p + 2 * (size_t)D_MODEL * D_MODEL;
    const __half* w3 = w16p + 3 * (size_t)D_MODEL * D_MODEL;

    cvt1_kernel<<<(MTOT * D_MODEL / 8 + 255) / 256, 256>>>((const float4*)x,
                                                           (uint4*)x16p,
                                                           MTOT * D_MODEL / 8);
    cvt4_kernel<<<dim3(D_MODEL * D_MODEL / 8 / 256, 4), 256>>>(
        (const float4*)Wq, (const float4*)Wk, (const float4*)Wv, (const float4*)Wo);

    // fused QKV projection (+RoPE, Q scale; all outputs fp16; V transposed)
    gemm_f16<<<dim3(D_MODEL / 128, MTOT / 128, 3), 128, GEMM_SMEM>>>(
        x16p, w0, w1, w2, out, q16p, k16p, vtp, 1, 3, 2, tp);

    flash_mma<<<dim3(SEQL / 64, BSZ * NH), 128, FLASH_SMEM>>>(a16p);

    // output projection (fp32 result)
    gemm_f16<<<dim3(D_MODEL / 128, MTOT / 128, 1), 128, GEMM_SMEM>>>(
        a16p, w3, w3, w3, out, q16p, k16p, vtp, 0, 0, 0, tp);
}

// round 10
// speedup vs baseline: 3.2148x; 1.0758x over previous
#include <cuda_runtime.h>
#include <cuda_fp16.h>
#include <math.h>
#include <stdint.h>

#define D_MODEL 1024
#define NH 16
#define HD 64
#define BSZ 2
#define SEQL 2048
#define MTOT (BSZ*SEQL)

// scratch (allocation-free) — fp16 pipeline
__device__ __half g_x16[(size_t)MTOT*D_MODEL];
__device__ __half g_w16[4][(size_t)D_MODEL*D_MODEL];
__device__ __half g_q16[(size_t)BSZ*NH*SEQL*HD];
__device__ __half g_k16[(size_t)BSZ*NH*SEQL*HD];
__device__ __half g_vt[(size_t)BSZ*NH*HD*SEQL];      // V transposed [bh][d][s]
__device__ __half g_attn16[(size_t)MTOT*D_MODEL];
__device__ float2 g_rope[(size_t)SEQL*(HD/2)];       // (cos,sin) per (s, pair)

// log2(e)/8 : folded into Q so softmax uses exp2
#define QSCALE 0.18033688011112042f

__device__ __forceinline__ uint32_t pf16x2(float lo, float hi) {
    uint32_t r;
    asm("cvt.rn.f16x2.f32 %0, %1, %2;" : "=r"(r) : "f"(hi), "f"(lo));
    return r;
}

__device__ __forceinline__ float ex2(float x) {
    float y;
    asm("ex2.approx.ftz.f32 %0, %1;" : "=f"(y) : "f"(x));
    return y;
}

__device__ __forceinline__ void mma_f16(float* c, uint32_t a0, uint32_t a1,
                                        uint32_t a2, uint32_t a3,
                                        uint32_t b0, uint32_t b1) {
    asm volatile(
        "mma.sync.aligned.m16n8k16.row.col.f32.f16.f16.f32 "
        "{%0,%1,%2,%3}, {%4,%5,%6,%7}, {%8,%9}, {%0,%1,%2,%3};"
        : "+f"(c[0]), "+f"(c[1]), "+f"(c[2]), "+f"(c[3])
        : "r"(a0), "r"(a1), "r"(a2), "r"(a3), "r"(b0), "r"(b1));
}

__device__ __forceinline__ void ldm4(uint32_t* r, uint32_t addr) {
    asm volatile("ldmatrix.sync.aligned.m8n8.x4.shared.b16 {%0,%1,%2,%3}, [%4];"
                 : "=r"(r[0]), "=r"(r[1]), "=r"(r[2]), "=r"(r[3]) : "r"(addr));
}

__device__ __forceinline__ void cpa16(uint32_t dst, const void* src) {
    asm volatile("cp.async.cg.shared.global [%0], [%1], 16;" :: "r"(dst), "l"(src));
}
__device__ __forceinline__ void cpa_commit() { asm volatile("cp.async.commit_group;"); }
__device__ __forceinline__ void cpa_wait2()  { asm volatile("cp.async.wait_group 2;"); }
__device__ __forceinline__ void cpa_wait1()  { asm volatile("cp.async.wait_group 1;"); }
__device__ __forceinline__ void cpa_wait0()  { asm volatile("cp.async.wait_group 0;"); }

// ---------------------------------------------------------------------------
// one-time tables / converts
// ---------------------------------------------------------------------------
__global__ void rope_kernel(const int* __restrict__ tokpos)
{
    int i = blockIdx.x * blockDim.x + threadIdx.x;   // 65536
    int s = i >> 5, j = i & 31;
    float pos = (float)tokpos[s];
    float fr = ex2((float)(2 * j) * (-13.287712379549449f / 64.f));
    float cs, sn;
    sincosf(pos * fr, &sn, &cs);
    g_rope[i] = make_float2(cs, sn);
}

__global__ void cvt1_kernel(const float4* __restrict__ src, uint4* __restrict__ dst, int n8)
{
    int i = blockIdx.x * blockDim.x + threadIdx.x;
    if (i < n8) {
        float4 a = src[2 * i], b = src[2 * i + 1];
        uint4 o;
        o.x = pf16x2(a.x, a.y); o.y = pf16x2(a.z, a.w);
        o.z = pf16x2(b.x, b.y); o.w = pf16x2(b.z, b.w);
        dst[i] = o;
    }
}

__global__ void cvt4_kernel(const float4* __restrict__ w0, const float4* __restrict__ w1,
                            const float4* __restrict__ w2, const float4* __restrict__ w3)
{
    int z = blockIdx.y;
    const float4* src = z == 0 ? w0 : z == 1 ? w1 : z == 2 ? w2 : w3;
    uint4* dst = (uint4*)g_w16[z];
    int i = blockIdx.x * blockDim.x + threadIdx.x;
    float4 a = src[2 * i], b = src[2 * i + 1];
    uint4 o;
    o.x = pf16x2(a.x, a.y); o.y = pf16x2(a.z, a.w);
    o.z = pf16x2(b.x, b.y); o.w = pf16x2(b.z, b.w);
    dst[i] = o;
}

// ---------------------------------------------------------------------------
// fp16 GEMM: Y[m,n] = sum_k A[m,k] * W[n,k]
// CTA tile 128x128, BK=32, 128 threads (4 warps), warp tile 64x64.
// ldmatrix.x4 fragment loads, 3-stage cp.async pipeline.
// mode 0: plain fp32 write; 1: RoPE*QSCALE -> fp16 scatter (Q);
// 3: RoPE -> fp16 scatter (K); 2: fp16 transposed scatter (V^T)
// ---------------------------------------------------------------------------
#define GSTR 40                          // fp16 units per row (80B, conflict-free)
#define GST (128*GSTR)                   // halves per (A or B) tile buffer
#define GEMM_SMEM (3*2*GST*2)            // 61440 B

__global__ __launch_bounds__(128)
void gemm_f16(const __half* __restrict__ A,
              const __half* __restrict__ W0, const __half* __restrict__ W1,
              const __half* __restrict__ W2,
              float* __restrict__ o0,
              __half* __restrict__ h0, __half* __restrict__ h1,
              __half* __restrict__ vt,
              int md0, int md1, int md2)
{
    extern __shared__ __half smh[];
    const int z = blockIdx.z;
    const __half* W = z == 0 ? W0 : z == 1 ? W1 : W2;
    const int mode = z == 0 ? md0 : z == 1 ? md1 : md2;
    __half* outh    = z == 0 ? h0 : h1;

    const int tid = (int)threadIdx.x;
    const int m0 = blockIdx.y * 128, n0 = blockIdx.x * 128;
    const int lane = tid & 31, wid = tid >> 5;
    const int g = lane >> 2, t = lane & 3;
    const int wm = (wid >> 1) * 64, wn = (wid & 1) * 64;

    uint32_t sbase = (uint32_t)__cvta_generic_to_shared(smh);

    const int aoff = (wm + (lane & 15)) * GSTR + (lane >> 4) * 8;
    const int boff = (wn + (lane >> 4) * 8 + (lane & 7)) * GSTR + ((lane >> 3) & 1) * 8;

    float c[4][8][4];
#pragma unroll
    for (int i = 0; i < 4; ++i)
#pragma unroll
        for (int j = 0; j < 8; ++j)
#pragma unroll
            for (int k = 0; k < 4; ++k) c[i][j][k] = 0.f;

#define ISSUE(stage, k0)                                                         \
    {                                                                            \
        uint32_t as_ = sbase + (uint32_t)(stage) * (2 * GST * 2);                \
        uint32_t bs_ = as_ + GST * 2;                                            \
        _Pragma("unroll")                                                        \
        for (int i_ = 0; i_ < 4; ++i_) {                                         \
            int lin_ = tid + i_ * 128;                                           \
            int row_ = lin_ >> 2;                                                \
            int cc_ = (lin_ & 3) * 8;                                            \
            cpa16(as_ + (uint32_t)(row_ * GSTR + cc_) * 2,                       \
                  A + (size_t)(m0 + row_) * D_MODEL + (k0) + cc_);               \
            cpa16(bs_ + (uint32_t)(row_ * GSTR + cc_) * 2,                       \
                  W + (size_t)(n0 + row_) * D_MODEL + (k0) + cc_);               \
        }                                                                        \
        cpa_commit();                                                            \
    }

    ISSUE(0, 0);
    ISSUE(1, 32);
    ISSUE(2, 64);

    int stage = 0;
    for (int kt = 0; kt < 32; ++kt) {
        cpa_wait2();
        __syncthreads();
        uint32_t abase = sbase + (uint32_t)stage * (2 * GST * 2) + (uint32_t)aoff * 2;
        uint32_t bbase = sbase + (uint32_t)stage * (2 * GST * 2) + GST * 2
                       + (uint32_t)boff * 2;

#pragma unroll
        for (int ks = 0; ks < 2; ++ks) {
            uint32_t af[4][4], bf[4][4];
#pragma unroll
            for (int mt = 0; mt < 4; ++mt)
                ldm4(af[mt], abase + (uint32_t)(mt * 16 * GSTR + ks * 16) * 2);
#pragma unroll
            for (int np = 0; np < 4; ++np)
                ldm4(bf[np], bbase + (uint32_t)(np * 16 * GSTR + ks * 16) * 2);
#pragma unroll
            for (int mt = 0; mt < 4; ++mt)
#pragma unroll
                for (int np = 0; np < 4; ++np) {
                    mma_f16(c[mt][2 * np],     af[mt][0], af[mt][1], af[mt][2],
                            af[mt][3], bf[np][0], bf[np][1]);
                    mma_f16(c[mt][2 * np + 1], af[mt][0], af[mt][1], af[mt][2],
                            af[mt][3], bf[np][2], bf[np][3]);
                }
        }
        __syncthreads();
        if (kt + 3 < 32) { ISSUE(stage, (kt + 3) * 32); }
        else             { cpa_commit(); }
        stage = stage == 2 ? 0 : stage + 1;
    }

    if (mode == 0) {
#pragma unroll
        for (int mt = 0; mt < 4; ++mt) {
            int rowa = m0 + wm + mt * 16 + g;
#pragma unroll
            for (int j = 0; j < 8; ++j) {
                int col = n0 + wn + j * 8 + 2 * t;
                *(float2*)(o0 + (size_t)rowa * D_MODEL + col) =
                    make_float2(c[mt][j][0], c[mt][j][1]);
                *(float2*)(o0 + (size_t)(rowa + 8) * D_MODEL + col) =
                    make_float2(c[mt][j][2], c[mt][j][3]);
            }
        }
    } else {
#pragma unroll
        for (int mt = 0; mt < 4; ++mt) {
#pragma unroll
            for (int half = 0; half < 2; ++half) {
                int m = m0 + wm + mt * 16 + g + half * 8;
                int b = m >> 11;
                int s = m & (SEQL - 1);
#pragma unroll
                for (int j = 0; j < 8; ++j) {
                    int col = n0 + wn + j * 8 + 2 * t;   // even
                    int h = col >> 6;
                    int d = col & 63;
                    float e = c[mt][j][half * 2 + 0];
                    float o = c[mt][j][half * 2 + 1];
                    if (mode != 2) {
                        float2 r = g_rope[s * 32 + (d >> 1)];
                        float re = e * r.x - o * r.y;
                        float ro = e * r.y + o * r.x;
                        if (mode == 1) { re *= QSCALE; ro *= QSCALE; }
                        size_t dst = ((size_t)(b * NH + h) * SEQL + s) * HD + d;
                        *(uint32_t*)(outh + dst) = pf16x2(re, ro);
                    } else {
                        size_t dst = ((size_t)(b * NH + h) * HD + d) * SEQL + s;
                        vt[dst]        = __float2half(e);
                        vt[dst + SEQL] = __float2half(o);
                    }
                }
            }
        }
    }
}

// ---------------------------------------------------------------------------
// Flash attention, all-fp16 mma. CTA: 128 threads (4 warps), QT=64, KT=64.
// P packed straight from QK C-fragments; V^T fp16 in smem; ex2.approx softmax.
// ---------------------------------------------------------------------------
#define FSTR 72
#define KBYTES (64 * FSTR * 2)
#define VBYTES (64 * FSTR * 2)
#define FLASH_SMEM (2 * KBYTES + 2 * VBYTES)

__device__ __forceinline__ void kv_issue(uint32_t sbase, int stage,
                                         const __half* Kp,
                                         const __half* Vtp,
                                         int tile, int tid)
{
    uint32_t dK = sbase + (uint32_t)stage * KBYTES;
    uint32_t dV = sbase + 2 * KBYTES + (uint32_t)stage * VBYTES;
#pragma unroll
    for (int i = 0; i < 4; ++i) {
        int lin = tid + i * 128;
        int row = lin >> 3;
        int cc = (lin & 7) * 8;
        cpa16(dK + (uint32_t)(row * FSTR + cc) * 2,
              Kp + (size_t)(tile * 64 + row) * HD + cc);
        cpa16(dV + (uint32_t)(row * FSTR + cc) * 2,
              Vtp + (size_t)row * SEQL + tile * 64 + cc);
    }
    cpa_commit();
}

__global__ __launch_bounds__(128)
void flash_mma(__half* __restrict__ attnout)
{
    extern __shared__ __half smh[];
    uint32_t sbase = (uint32_t)__cvta_generic_to_shared(smh);

    const int qt = (int)(gridDim.x - 1 - blockIdx.x);
    const int bh = (int)blockIdx.y;
    const int b  = bh >> 4;
    const int h  = bh & 15;
    const int tid = (int)threadIdx.x;
    const int wid = tid >> 5, lane = tid & 31;
    const int g = lane >> 2, t = lane & 3;
    const int wm = wid * 16;

    const __half* Qp = g_q16 + (size_t)bh * SEQL * HD;
    const __half* Kp = g_k16 + (size_t)bh * SEQL * HD;
    const __half* Vtp = g_vt + (size_t)bh * HD * SEQL;

#pragma unroll
    for (int i = 0; i < 4; ++i) {
        int lin = tid + i * 128;
        int row = lin >> 3;
        int cc = (lin & 7) * 8;
        *(uint4*)&smh[row * FSTR + cc] =
            *(const uint4*)(Qp + (size_t)(qt * 64 + row) * HD + cc);
    }
    __syncthreads();
    uint32_t aq[4][4];
#pragma unroll
    for (int ks = 0; ks < 4; ++ks) {
        const __half* p = smh + (wm + g) * FSTR + ks * 16 + 2 * t;
        aq[ks][0] = *(const uint32_t*)p;
        aq[ks][1] = *(const uint32_t*)(p + 8 * FSTR);
        aq[ks][2] = *(const uint32_t*)(p + 8);
        aq[ks][3] = *(const uint32_t*)(p + 8 * FSTR + 8);
    }
    __syncthreads();

    float m0 = -1e30f, m1 = -1e30f, l0 = 0.f, l1 = 0.f;
    float o[8][4];
#pragma unroll
    for (int n = 0; n < 8; ++n)
#pragma unroll
        for (int e = 0; e < 4; ++e) o[n][e] = 0.f;

    kv_issue(sbase, 0, Kp, Vtp, 0, tid);
    if (qt > 0) kv_issue(sbase, 1, Kp, Vtp, 1, tid);

    for (int kt = 0; kt <= qt; ++kt) {
        const int cur = kt & 1;
        if (kt < qt) cpa_wait1(); else cpa_wait0();
        __syncthreads();
        const __half* K0 = smh + cur * (KBYTES / 2);
        const __half* Vt = smh + (2 * KBYTES + cur * VBYTES) / 2;

        float cs[8][4];
#pragma unroll
        for (int n = 0; n < 8; ++n)
#pragma unroll
            for (int e = 0; e < 4; ++e) cs[n][e] = 0.f;
#pragma unroll
        for (int ks = 0; ks < 4; ++ks) {
#pragma unroll
            for (int n = 0; n < 8; ++n) {
                const __half* kb = K0 + (n * 8 + g) * FSTR + ks * 16 + 2 * t;
                mma_f16(cs[n], aq[ks][0], aq[ks][1], aq[ks][2], aq[ks][3],
                        *(const uint32_t*)kb, *(const uint32_t*)(kb + 8));
            }
        }

        if (kt == qt) {
            const int rowg = wm + g;
#pragma unroll
            for (int n = 0; n < 8; ++n) {
                int col = n * 8 + 2 * t;
                if (col     > rowg)     cs[n][0] = -1e30f;
                if (col + 1 > rowg)     cs[n][1] = -1e30f;
                if (col     > rowg + 8) cs[n][2] = -1e30f;
                if (col + 1 > rowg + 8) cs[n][3] = -1e30f;
            }
        }

        float mx0 = -1e30f, mx1 = -1e30f;
#pragma unroll
        for (int n = 0; n < 8; ++n) {
            mx0 = fmaxf(mx0, fmaxf(cs[n][0], cs[n][1]));
            mx1 = fmaxf(mx1, fmaxf(cs[n][2], cs[n][3]));
        }
        mx0 = fmaxf(mx0, __shfl_xor_sync(0xffffffffu, mx0, 1));
        mx0 = fmaxf(mx0, __shfl_xor_sync(0xffffffffu, mx0, 2));
        mx1 = fmaxf(mx1, __shfl_xor_sync(0xffffffffu, mx1, 1));
        mx1 = fmaxf(mx1, __shfl_xor_sync(0xffffffffu, mx1, 2));
        float mn0 = fmaxf(m0, mx0), mn1 = fmaxf(m1, mx1);
        float a0 = ex2(m0 - mn0), a1 = ex2(m1 - mn1);

        float s0 = 0.f, s1 = 0.f;
        uint32_t pa0[8], pa1[8];
#pragma unroll
        for (int n = 0; n < 8; ++n) {
            float p00 = ex2(cs[n][0] - mn0);
            float p01 = ex2(cs[n][1] - mn0);
            float p10 = ex2(cs[n][2] - mn1);
            float p11 = ex2(cs[n][3] - mn1);
            s0 += p00 + p01;
            s1 += p10 + p11;
            pa0[n] = pf16x2(p00, p01);
            pa1[n] = pf16x2(p10, p11);
        }
        s0 += __shfl_xor_sync(0xffffffffu, s0, 1);
        s0 += __shfl_xor_sync(0xffffffffu, s0, 2);
        s1 += __shfl_xor_sync(0xffffffffu, s1, 1);
        s1 += __shfl_xor_sync(0xffffffffu, s1, 2);
        l0 = l0 * a0 + s0;
        l1 = l1 * a1 + s1;
        m0 = mn0; m1 = mn1;
#pragma unroll
        for (int n = 0; n < 8; ++n) {
            o[n][0] *= a0; o[n][1] *= a0;
            o[n][2] *= a1; o[n][3] *= a1;
        }

#pragma unroll
        for (int ks = 0; ks < 4; ++ks) {
            uint32_t a0r = pa0[2 * ks],     a1r = pa1[2 * ks];
            uint32_t a2r = pa0[2 * ks + 1], a3r = pa1[2 * ks + 1];
#pragma unroll
            for (int n = 0; n < 8; ++n) {
                const __half* vb = Vt + (n * 8 + g) * FSTR + ks * 16 + 2 * t;
                mma_f16(o[n], a0r, a1r, a2r, a3r,
                        *(const uint32_t*)vb, *(const uint32_t*)(vb + 8));
            }
        }
        __syncthreads();
        if (kt + 2 <= qt) kv_issue(sbase, cur, Kp, Vtp, kt + 2, tid);
    }

    float i0 = 1.f / l0, i1 = 1.f / l1;
    __half* d0 = attnout + ((size_t)(b * SEQL) + qt * 64 + wm + g) * D_MODEL + h * HD;
#pragma unroll
    for (int n = 0; n < 8; ++n) {
        int col = n * 8 + 2 * t;
        *(uint32_t*)(d0 + col) = pf16x2(o[n][0] * i0, o[n][1] * i0);
        *(uint32_t*)(d0 + 8 * D_MODEL + col) = pf16x2(o[n][2] * i1, o[n][3] * i1);
    }
}

// ---------------------------------------------------------------------------
extern "C" void kernel_launch(void* const* d_in, const int* in_sizes, int n_in,
                              void* d_out, int out_size)
{
    const float* x  = (const float*)d_in[0];
    const int*   tp = (const int*)d_in[1];
    const float* Wq = (const float*)d_in[2];
    const float* Wk = (const float*)d_in[3];
    const float* Wv = (const float*)d_in[4];
    const float* Wo = (const float*)d_in[5];
    float* out = (float*)d_out;

    __half *x16p, *w16p, *q16p, *k16p, *vtp, *a16p;
    cudaGetSymbolAddress((void**)&x16p, g_x16);
    cudaGetSymbolAddress((void**)&w16p, g_w16);
    cudaGetSymbolAddress((void**)&q16p, g_q16);
    cudaGetSymbolAddress((void**)&k16p, g_k16);
    cudaGetSymbolAddress((void**)&vtp, g_vt);
    cudaGetSymbolAddress((void**)&a16p, g_attn16);

    static int inited = 0;
    if (!inited) {
        cudaFuncSetAttribute(gemm_f16, cudaFuncAttributeMaxDynamicSharedMemorySize,
                             GEMM_SMEM);
        cudaFuncSetAttribute(flash_mma, cudaFuncAttributeMaxDynamicSharedMemorySize,
                             FLASH_SMEM);
        inited = 1;
    }

    const __half* w0 = w16p;
    const __half* w1 = w16p + (size_t)D_MODEL * D_MODEL;
    const __half* w2 = w16p + 2 * (size_t)D_MODEL * D_MODEL;
    const __half* w3 = w16p + 3 * (size_t)D_MODEL * D_MODEL;

    rope_kernel<<<SEQL * 32 / 256, 256>>>(tp);
    cvt1_kernel<<<(MTOT * D_MODEL / 8 + 255) / 256, 256>>>((const float4*)x,
                                                           (uint4*)x16p,
                                                           MTOT * D_MODEL / 8);
    cvt4_kernel<<<dim3(D_MODEL * D_MODEL / 8 / 256, 4), 256>>>(
        (const float4*)Wq, (const float4*)Wk, (const float4*)Wv, (const float4*)Wo);

    // fused QKV projection (+RoPE table, Q scale; fp16 outputs; V transposed)
    gemm_f16<<<dim3(D_MODEL / 128, MTOT / 128, 3), 128, GEMM_SMEM>>>(
        x16p, w0, w1, w2, out, q16p, k16p, vtp, 1, 3, 2);

    flash_mma<<<dim3(SEQL / 64, BSZ * NH), 128, FLASH_SMEM>>>(a16p);

    // output projection (fp32 result)
    gemm_f16<<<dim3(D_MODEL / 128, MTOT / 128, 1), 128, GEMM_SMEM>>>(
        a16p, w3, w3, w3, out, q16p, k16p, vtp, 0, 0, 0);
}